// round 10
// baseline (speedup 1.0000x reference)
#include <cuda_runtime.h>
#include <cuda_fp16.h>
#include <cstdint>

#define B_ 8
#define L_ 1024
#define D_ 512
#define H_ 8
#define DK_ 64
#define M_ (B_*L_)

// Scratch (no allocations allowed)
__device__ __half g_Ah[3][M_*D_];   // fp16 query/key/value
__device__ __half g_Wh[4][D_*D_];   // fp16 Wq,Wk,Wv,Wo
__device__ __half g_Q[B_*H_*L_*DK_];
__device__ __half g_K[B_*H_*L_*DK_];
__device__ __half g_V[B_*H_*L_*DK_];
__device__ __half g_X[M_*D_];
__device__ __half g_DM[B_*L_*L_];   // fp16 dist with mask folded in

// ---------------------------------------------------------------------------
// helpers
// ---------------------------------------------------------------------------
__device__ __forceinline__ uint32_t smem_to_u32(const void* p) {
    uint32_t a;
    asm("{ .reg .u64 t; cvta.to.shared.u64 t, %1; cvt.u32.u64 %0, t; }"
        : "=r"(a) : "l"(p));
    return a;
}
__device__ __forceinline__ void cp16(uint32_t dst, const void* src) {
    asm volatile("cp.async.cg.shared.global [%0], [%1], 16;"
                 :: "r"(dst), "l"(src));
}
#define CP_COMMIT asm volatile("cp.async.commit_group;")
#define CP_WAIT(n) asm volatile("cp.async.wait_group %0;" :: "n"(n))

__device__ __forceinline__ void ldsm4(uint32_t* r, uint32_t addr) {
    asm volatile("ldmatrix.sync.aligned.m8n8.x4.shared.b16 {%0,%1,%2,%3}, [%4];"
        : "=r"(r[0]), "=r"(r[1]), "=r"(r[2]), "=r"(r[3]) : "r"(addr));
}
__device__ __forceinline__ void ldsm4t(uint32_t* r, uint32_t addr) {
    asm volatile("ldmatrix.sync.aligned.m8n8.x4.trans.shared.b16 {%0,%1,%2,%3}, [%4];"
        : "=r"(r[0]), "=r"(r[1]), "=r"(r[2]), "=r"(r[3]) : "r"(addr));
}
__device__ __forceinline__ void mma_f16(float* c, const uint32_t* a, const uint32_t* b) {
    asm volatile(
        "mma.sync.aligned.m16n8k16.row.col.f32.f16.f16.f32 "
        "{%0,%1,%2,%3}, {%4,%5,%6,%7}, {%8,%9}, {%0,%1,%2,%3};"
        : "+f"(c[0]), "+f"(c[1]), "+f"(c[2]), "+f"(c[3])
        : "r"(a[0]), "r"(a[1]), "r"(a[2]), "r"(a[3]), "r"(b[0]), "r"(b[1]));
}
__device__ __forceinline__ uint32_t h2u(__half2 h) { return *(uint32_t*)&h; }
__device__ __forceinline__ float ex2(float x) {
    float r;
    asm("ex2.approx.f32 %0, %1;" : "=f"(r) : "f"(x));
    return r;
}
// shared-space 32-bit load (avoids generic/shared address mixing)
__device__ __forceinline__ uint32_t lds32(uint32_t addr) {
    uint32_t v;
    asm volatile("ld.shared.b32 %0, [%1];" : "=r"(v) : "r"(addr));
    return v;
}

// ===========================================================================
// fp32 -> fp16 convert pass (8 elems/thread)
// ===========================================================================
__global__ void cvt_kernel(const float4* __restrict__ s0, const float4* __restrict__ s1,
                           const float4* __restrict__ s2, const float4* __restrict__ s3,
                           uint4* d0, uint4* d1, uint4* d2, uint4* d3)
{
    const int z = blockIdx.z;
    const float4* s = (z == 0) ? s0 : (z == 1) ? s1 : (z == 2) ? s2 : s3;
    uint4* d = (z == 0) ? d0 : (z == 1) ? d1 : (z == 2) ? d2 : d3;
    const int i = blockIdx.x * blockDim.x + threadIdx.x;
    float4 u = s[2 * i], v = s[2 * i + 1];
    uint4 o;
    o.x = h2u(__floats2half2_rn(u.x, u.y));
    o.y = h2u(__floats2half2_rn(u.z, u.w));
    o.z = h2u(__floats2half2_rn(v.x, v.y));
    o.w = h2u(__floats2half2_rn(v.z, v.w));
    d[i] = o;
}

// dist + mask -> fp16 dmc (masked entries become 6e4, i.e. exp -> 0)
__global__ void cvtdist_kernel(const float4* __restrict__ dist,
                               const uchar4* __restrict__ mask,
                               uint4* __restrict__ out)
{
    const int i = blockIdx.x * blockDim.x + threadIdx.x;
    float4 a = dist[2 * i], b = dist[2 * i + 1];
    uchar4 ma = mask[2 * i], mb = mask[2 * i + 1];
    if (ma.x) a.x = 60000.f;
    if (ma.y) a.y = 60000.f;
    if (ma.z) a.z = 60000.f;
    if (ma.w) a.w = 60000.f;
    if (mb.x) b.x = 60000.f;
    if (mb.y) b.y = 60000.f;
    if (mb.z) b.z = 60000.f;
    if (mb.w) b.w = 60000.f;
    uint4 o;
    o.x = h2u(__floats2half2_rn(a.x, a.y));
    o.y = h2u(__floats2half2_rn(a.z, a.w));
    o.z = h2u(__floats2half2_rn(b.x, b.y));
    o.w = h2u(__floats2half2_rn(b.z, b.w));
    out[i] = o;
}

// ===========================================================================
// Fused projection GEMM (fp16 in, fp32 accum): C_z = A_z * W_z^T + bias_z
// Tile 128m x 128n x 64k, 3-stage cp.async, 8 warps (4m x 2n, 32x64 each).
// ===========================================================================
#define GBM 128
#define GBN 128
#define GBK 64
#define GKT (D_ / GBK)               // 8
#define GA(s) ((s) * 16384)          // A: 128 rows x 128B
#define GB(s) (49152 + (s) * 16384)  // W: 128 rows x 128B
#define GSM 98304

__global__ __launch_bounds__(256) void gemm3_kernel(
    const __half* __restrict__ A0, const __half* __restrict__ A1, const __half* __restrict__ A2,
    const __half* __restrict__ W0, const __half* __restrict__ W1, const __half* __restrict__ W2,
    const float* __restrict__ bp0, const float* __restrict__ bp1, const float* __restrict__ bp2,
    __half* __restrict__ Ch0, __half* __restrict__ Ch1, __half* __restrict__ Ch2,
    float* __restrict__ Cf, int heads)
{
    extern __shared__ char sm[];
    const uint32_t sb = smem_to_u32(sm);
    const int z = blockIdx.z;
    const __half* A    = (z == 0) ? A0 : (z == 1) ? A1 : A2;
    const __half* W    = (z == 0) ? W0 : (z == 1) ? W1 : W2;
    const float* bias  = (z == 0) ? bp0 : (z == 1) ? bp1 : bp2;
    __half* Ch         = (z == 0) ? Ch0 : (z == 1) ? Ch1 : Ch2;

    const int tid = threadIdx.x;
    const int lane = tid & 31, warp = tid >> 5;
    const int wm = warp >> 1, wn = warp & 1;
    const int g = lane >> 2, t = lane & 3;
    const int m0 = blockIdx.y * GBM, n0 = blockIdx.x * GBN;

    auto stage = [&](int kt, int s) {
        const __half* Ab = A + (size_t)m0 * D_ + kt * GBK;
        const __half* Wb = W + (size_t)n0 * D_ + kt * GBK;
#pragma unroll
        for (int i = 0; i < 4; ++i) {          // A and W: 128 rows x 8 chunks each
            int ci = tid + 256 * i;
            int row = ci >> 3, ch = ci & 7;
            uint32_t off = row * 128 + ((ch ^ (row & 7)) << 4);
            cp16(sb + GA(s) + off, Ab + (size_t)row * D_ + ch * 8);
            cp16(sb + GB(s) + off, Wb + (size_t)row * D_ + ch * 8);
        }
        CP_COMMIT;
    };

    stage(0, 0);
    stage(1, 1);

    const int l7 = lane & 7;
    const int rowA = wm * 32 + l7 + ((lane >> 3) & 1) * 8;   // + mt*16
    const int kchA = lane >> 4;
    const int rowB = wn * 64 + l7 + (lane >> 4) * 8;         // + ntp*16
    const int kchB = (lane >> 3) & 1;

    float acc[2][8][4] = {};

#pragma unroll 1
    for (int kt = 0; kt < GKT; ++kt) {
        if (kt < GKT - 1) { CP_WAIT(1); } else { CP_WAIT(0); }
        __syncthreads();
        if (kt + 2 < GKT) stage(kt + 2, (kt + 2) % 3);

        const uint32_t Ao = sb + GA(kt % 3), Bo = sb + GB(kt % 3);
#pragma unroll
        for (int kk = 0; kk < 4; ++kk) {
            uint32_t a[2][4], b[4][4];
#pragma unroll
            for (int mt = 0; mt < 2; ++mt)
                ldsm4(a[mt], Ao + (uint32_t)(rowA + mt * 16) * 128
                             + (((2 * kk + kchA) ^ l7) << 4));
#pragma unroll
            for (int ntp = 0; ntp < 4; ++ntp)
                ldsm4(b[ntp], Bo + (uint32_t)(rowB + ntp * 16) * 128
                              + (((2 * kk + kchB) ^ l7) << 4));
#pragma unroll
            for (int mt = 0; mt < 2; ++mt)
#pragma unroll
                for (int nt = 0; nt < 8; ++nt)
                    mma_f16(acc[mt][nt], a[mt], &b[nt >> 1][(nt & 1) * 2]);
        }
    }

    // Epilogue
#pragma unroll
    for (int mt = 0; mt < 2; ++mt) {
#pragma unroll
        for (int nt = 0; nt < 8; ++nt) {
            int n = n0 + wn * 64 + nt * 8 + 2 * t;
            float2 bv = *(const float2*)&bias[n];
            float2 r0, r1;
            r0.x = acc[mt][nt][0] + bv.x; r0.y = acc[mt][nt][1] + bv.y;
            r1.x = acc[mt][nt][2] + bv.x; r1.y = acc[mt][nt][3] + bv.y;
            int m_a = m0 + wm * 32 + mt * 16 + g;
            int m_b = m_a + 8;
            if (heads) {
                int h = n >> 6, dk = n & 63;
                int ba = m_a >> 10, la = m_a & (L_ - 1);
                int bb = m_b >> 10, lb = m_b & (L_ - 1);
                *(__half2*)&Ch[((size_t)(ba * H_ + h) * L_ + la) * DK_ + dk] =
                    __floats2half2_rn(r0.x, r0.y);
                *(__half2*)&Ch[((size_t)(bb * H_ + h) * L_ + lb) * DK_ + dk] =
                    __floats2half2_rn(r1.x, r1.y);
            } else {
                *(float2*)&Cf[(size_t)m_a * D_ + n] = r0;
                *(float2*)&Cf[(size_t)m_b * D_ + n] = r1;
            }
        }
    }
}

// ===========================================================================
// Flash attention, fp16 mma + ldmatrix, cp.async K(x2)/V(x3)/dmc(x2) bufs.
// 512 threads, 128 q-rows per CTA (16 warps, 8m x 2n, 16x32 per warp).
// Softmax in log2 domain (ex2.approx). No hot-loop LDG at all.
// ===========================================================================
#define ATH 512
#define AQ 0
#define APof 16384
#define AK(s) (32768 + (s) * 8192)    // 2 bufs (64x64 fp16)
#define AV(s) (49152 + (s) * 8192)    // 3 bufs
#define ADM(s) (73728 + (s) * 16384)  // 2 bufs (128q x 64k fp16)
#define ARM 106496                    // redm: 2 x 128 floats
#define ARS 107520                    // reds: 2 x 128 floats
#define ASMs 108544

__global__ __launch_bounds__(ATH) void attn_kernel(
    const __half* __restrict__ Q, const __half* __restrict__ K,
    const __half* __restrict__ V, const __half* __restrict__ dmc,
    const float* __restrict__ logwb, __half* __restrict__ X)
{
    extern __shared__ char sm[];
    const uint32_t sb = smem_to_u32(sm);
    float* redm = (float*)(sm + ARM);
    float* reds = (float*)(sm + ARS);

    const int tid = threadIdx.x;
    const int lane = tid & 31, warp = tid >> 5;
    const int wm = warp >> 1, wn = warp & 1;   // 8m x 2n
    const int g = lane >> 2, t = lane & 3;
    const int l7 = lane & 7;
    const int bh = blockIdx.y;
    const int b = bh >> 3, h = bh & 7;
    const int q0 = blockIdx.x * 128;
    const float LOG2E = 1.4426950408889634f;
    const float wb2 = __expf(logwb[h]) * LOG2E;
    const float c1 = 0.125f * LOG2E;
    const int qr = wm * 16;                    // 0..112

    const __half* Qb = Q + (size_t)(bh * L_ + q0) * DK_;
    const __half* Kb = K + (size_t)bh * L_ * DK_;
    const __half* Vb = V + (size_t)bh * L_ * DK_;
    const __half* Db = dmc + (size_t)b * L_ * L_ + (size_t)q0 * L_;

    auto stageKVD = [&](int tile, int kbuf, int vbuf, int dbuf) {
        const __half* Kt = Kb + (size_t)tile * 64 * DK_;
        const __half* Vt = Vb + (size_t)tile * 64 * DK_;
        const __half* Dt = Db + tile * 64;
        {   // K + V: 64 rows x 8 chunks each, one pass of 512 threads
            int row = tid >> 3, ch = tid & 7;
            uint32_t off = row * 128 + ((ch ^ (row & 7)) << 4);
            cp16(sb + AK(kbuf) + off, Kt + row * DK_ + ch * 8);
            cp16(sb + AV(vbuf) + off, Vt + row * DK_ + ch * 8);
        }
#pragma unroll
        for (int i = 0; i < 2; ++i) {  // dmc: 128 rows x 8 chunks
            int ci = tid + ATH * i;
            int row = ci >> 3, ch = ci & 7;
            uint32_t off = row * 128 + ((ch ^ (row & 7)) << 4);
            cp16(sb + ADM(dbuf) + off, Dt + (size_t)row * L_ + ch * 8);
        }
        CP_COMMIT;
    };

    // Stage Q (128 rows), then tiles 0 and 1
    {
#pragma unroll
        for (int i = 0; i < 2; ++i) {
            int ci = tid + ATH * i;
            int row = ci >> 3, ch = ci & 7;
            cp16(sb + AQ + row * 128 + ((ch ^ (row & 7)) << 4),
                 Qb + row * DK_ + ch * 8);
        }
        CP_COMMIT;
    }
    stageKVD(0, 0, 0, 0);
    stageKVD(1, 1, 1, 1);

    CP_WAIT(2);
    __syncthreads();

    // Q fragments (kept in regs whole loop)
    uint32_t qa[4][4];
#pragma unroll
    for (int kk = 0; kk < 4; ++kk)
        ldsm4(qa[kk], sb + AQ + (uint32_t)(qr + l7 + ((lane >> 3) & 1) * 8) * 128
                      + (((2 * kk + (lane >> 4)) ^ l7) << 4));

    float o[4][4] = {};
    float mrow0 = -1e30f, mrow1 = -1e30f;
    float lrow0 = 0.f, lrow1 = 0.f;

    // ldmatrix / LDS per-lane geometry
    const int keyB = wn * 32 + l7 + (lane >> 4) * 8;
    const int kchB = (lane >> 3) & 1;
    const int rowP = qr + l7 + ((lane >> 3) & 1) * 8;
    const int kchP = lane >> 4;
    const int keyV = l7 + ((lane >> 3) & 1) * 8;
    const int dchV = wn * 4 + (lane >> 4);
    const uint32_t dmr0 = (uint32_t)(qr + g) * 128 + 4 * t;
    const uint32_t dmr1 = dmr0 + 8 * 128;

#pragma unroll 1
    for (int it = 0; it < 16; ++it) {
        if (it < 15) { CP_WAIT(1); } else { CP_WAIT(0); }
        __syncthreads();                       // sync1: tile `it` staged
        const uint32_t Ko = sb + AK(it & 1), Vo = sb + AV(it % 3);
        const uint32_t Do = sb + ADM(it & 1);

        // S = Q K^T
        float s[4][4] = {};
#pragma unroll
        for (int kk = 0; kk < 4; ++kk) {
            uint32_t kb[2][4];
#pragma unroll
            for (int ntp = 0; ntp < 2; ++ntp)
                ldsm4(kb[ntp], Ko + (uint32_t)(keyB + ntp * 16) * 128
                               + (((2 * kk + kchB) ^ l7) << 4));
#pragma unroll
            for (int nt = 0; nt < 4; ++nt)
                mma_f16(s[nt], qa[kk], &kb[nt >> 1][(nt & 1) * 2]);
        }

        // bias from smem dmc tile: s2 = qk*c1 - d*wb2 (log2 domain)
#pragma unroll
        for (int nt = 0; nt < 4; ++nt) {
            uint32_t co = (uint32_t)(((4 * wn + nt) ^ g) << 4);
            uint32_t du0 = lds32(Do + dmr0 + co);
            uint32_t du1 = lds32(Do + dmr1 + co);
            float2 d0 = __half22float2(*(__half2*)&du0);
            float2 d1 = __half22float2(*(__half2*)&du1);
            s[nt][0] = fmaf(s[nt][0], c1, -d0.x * wb2);
            s[nt][1] = fmaf(s[nt][1], c1, -d0.y * wb2);
            s[nt][2] = fmaf(s[nt][2], c1, -d1.x * wb2);
            s[nt][3] = fmaf(s[nt][3], c1, -d1.y * wb2);
        }

        // row max
        float tm0 = -1e30f, tm1 = -1e30f;
#pragma unroll
        for (int nt = 0; nt < 4; ++nt) {
            tm0 = fmaxf(tm0, fmaxf(s[nt][0], s[nt][1]));
            tm1 = fmaxf(tm1, fmaxf(s[nt][2], s[nt][3]));
        }
        tm0 = fmaxf(tm0, __shfl_xor_sync(0xffffffff, tm0, 1));
        tm0 = fmaxf(tm0, __shfl_xor_sync(0xffffffff, tm0, 2));
        tm1 = fmaxf(tm1, __shfl_xor_sync(0xffffffff, tm1, 1));
        tm1 = fmaxf(tm1, __shfl_xor_sync(0xffffffff, tm1, 2));
        if (t == 0) {
            redm[wn * 128 + qr + g] = tm0;
            redm[wn * 128 + qr + g + 8] = tm1;
        }
        __syncthreads();                       // sync2: K/dmc reads + redm done

        // stage tile it+2 into freed buffers
        if (it + 2 < 16) stageKVD(it + 2, it & 1, (it + 2) % 3, it & 1);

        float mn0 = fmaxf(mrow0, fmaxf(redm[qr + g], redm[128 + qr + g]));
        float mn1 = fmaxf(mrow1, fmaxf(redm[qr + g + 8], redm[128 + qr + g + 8]));
        float sc0 = ex2(mrow0 - mn0);
        float sc1 = ex2(mrow1 - mn1);
        mrow0 = mn0; mrow1 = mn1;

        // P = ex2(s - m) -> fp16 P tile, partial sums
        const uint32_t prow0 = sb + APof + (uint32_t)(qr + g) * 128;
        const uint32_t prow1 = prow0 + 8 * 128;
        float sum0 = 0.f, sum1 = 0.f;
#pragma unroll
        for (int nt = 0; nt < 4; ++nt) {
            int c = wn * 32 + nt * 8 + 2 * t;
            float p00 = ex2(s[nt][0] - mn0);
            float p01 = ex2(s[nt][1] - mn0);
            float p10 = ex2(s[nt][2] - mn1);
            float p11 = ex2(s[nt][3] - mn1);
            uint32_t off = ((((uint32_t)c >> 3) ^ (uint32_t)g) << 4) + (c & 7) * 2;
            __half2 hp0 = __floats2half2_rn(p00, p01);
            __half2 hp1 = __floats2half2_rn(p10, p11);
            asm volatile("st.shared.b32 [%0], %1;" :: "r"(prow0 + off), "r"(h2u(hp0)));
            asm volatile("st.shared.b32 [%0], %1;" :: "r"(prow1 + off), "r"(h2u(hp1)));
            sum0 += p00 + p01;
            sum1 += p10 + p11;
        }
        sum0 += __shfl_xor_sync(0xffffffff, sum0, 1);
        sum0 += __shfl_xor_sync(0xffffffff, sum0, 2);
        sum1 += __shfl_xor_sync(0xffffffff, sum1, 1);
        sum1 += __shfl_xor_sync(0xffffffff, sum1, 2);
        if (t == 0) {
            reds[wn * 128 + qr + g] = sum0;
            reds[wn * 128 + qr + g + 8] = sum1;
        }

        // rescale O
#pragma unroll
        for (int nt = 0; nt < 4; ++nt) {
            o[nt][0] *= sc0; o[nt][1] *= sc0;
            o[nt][2] *= sc1; o[nt][3] *= sc1;
        }
        __syncthreads();                       // sync3: P + reds visible

        lrow0 = lrow0 * sc0 + reds[qr + g] + reds[128 + qr + g];
        lrow1 = lrow1 * sc1 + reds[qr + g + 8] + reds[128 + qr + g + 8];

        // O += P V
#pragma unroll
        for (int kk = 0; kk < 4; ++kk) {
            uint32_t pa[4], vb[2][4];
            ldsm4(pa, sb + APof + (uint32_t)rowP * 128
                      + (((2 * kk + kchP) ^ l7) << 4));
#pragma unroll
            for (int ntp = 0; ntp < 2; ++ntp)
                ldsm4t(vb[ntp], Vo + (uint32_t)(kk * 16 + keyV) * 128
                                + (((dchV + ntp * 2) ^ l7) << 4));
#pragma unroll
            for (int nt = 0; nt < 4; ++nt)
                mma_f16(o[nt], pa, &vb[nt >> 1][(nt & 1) * 2]);
        }
    }

    // Normalize, write X (fp16) in (B, L, D)
    float inv0 = 1.f / lrow0;
    float inv1 = 1.f / lrow1;
    const size_t xr0 = (size_t)(b * L_ + q0 + qr + g) * D_ + h * DK_;
    const size_t xr1 = xr0 + 8 * D_;
#pragma unroll
    for (int nt = 0; nt < 4; ++nt) {
        int c = wn * 32 + nt * 8 + 2 * t;
        *(__half2*)&X[xr0 + c] = __floats2half2_rn(o[nt][0] * inv0, o[nt][1] * inv0);
        *(__half2*)&X[xr1 + c] = __floats2half2_rn(o[nt][2] * inv1, o[nt][3] * inv1);
    }
}

// ---------------------------------------------------------------------------
extern "C" void kernel_launch(void* const* d_in, const int* in_sizes, int n_in,
                              void* d_out, int out_size)
{
    const float* query = (const float*)d_in[0];
    const float* key_  = (const float*)d_in[1];
    const float* value = (const float*)d_in[2];
    const float* dist  = (const float*)d_in[3];
    const unsigned char* mask = (const unsigned char*)d_in[4];
    const float* Wq = (const float*)d_in[5];
    const float* bq = (const float*)d_in[6];
    const float* Wk = (const float*)d_in[7];
    const float* bk = (const float*)d_in[8];
    const float* Wv = (const float*)d_in[9];
    const float* bv = (const float*)d_in[10];
    const float* Wo = (const float*)d_in[11];
    const float* bo = (const float*)d_in[12];
    const float* logwb = (const float*)d_in[13];

    __half *Ah, *Wh, *Qp, *Kp, *Vp, *Xp, *Dp;
    cudaGetSymbolAddress((void**)&Ah, g_Ah);
    cudaGetSymbolAddress((void**)&Wh, g_Wh);
    cudaGetSymbolAddress((void**)&Qp, g_Q);
    cudaGetSymbolAddress((void**)&Kp, g_K);
    cudaGetSymbolAddress((void**)&Vp, g_V);
    cudaGetSymbolAddress((void**)&Xp, g_X);
    cudaGetSymbolAddress((void**)&Dp, g_DM);
    __half* A0 = Ah;            __half* A1 = Ah + (size_t)M_ * D_;
    __half* A2 = Ah + 2 * (size_t)M_ * D_;
    __half* W0 = Wh;            __half* W1 = Wh + (size_t)D_ * D_;
    __half* W2 = Wh + 2 * (size_t)D_ * D_;
    __half* W3 = Wh + 3 * (size_t)D_ * D_;

    cudaFuncSetAttribute(gemm3_kernel,
                         cudaFuncAttributeMaxDynamicSharedMemorySize, GSM);
    cudaFuncSetAttribute(attn_kernel,
                         cudaFuncAttributeMaxDynamicSharedMemorySize, ASMs);

    // fp32 -> fp16 conversion passes
    cvt_kernel<<<dim3(M_ * D_ / (8 * 256), 1, 3), 256>>>(
        (const float4*)query, (const float4*)key_, (const float4*)value,
        (const float4*)query,
        (uint4*)A0, (uint4*)A1, (uint4*)A2, (uint4*)A0);
    cvt_kernel<<<dim3(D_ * D_ / (8 * 256), 1, 4), 256>>>(
        (const float4*)Wq, (const float4*)Wk, (const float4*)Wv, (const float4*)Wo,
        (uint4*)W0, (uint4*)W1, (uint4*)W2, (uint4*)W3);
    cvtdist_kernel<<<B_ * L_ * L_ / (8 * 256), 256>>>(
        (const float4*)dist, (const uchar4*)mask, (uint4*)Dp);

    // Fused Q/K/V projections
    gemm3_kernel<<<dim3(D_ / GBN, M_ / GBM, 3), 256, GSM>>>(
        A0, A1, A2, W0, W1, W2, bq, bk, bv, Qp, Kp, Vp, nullptr, 1);

    attn_kernel<<<dim3(L_ / 128, B_ * H_), ATH, ASMs>>>(
        Qp, Kp, Vp, Dp, logwb, Xp);

    // Output projection (fp32 out)
    gemm3_kernel<<<dim3(D_ / GBN, M_ / GBM, 1), 256, GSM>>>(
        Xp, Xp, Xp, W3, W3, W3, bo, bo, bo,
        nullptr, nullptr, nullptr, (float*)d_out, 0);
}

// round 11
// speedup vs baseline: 1.2739x; 1.2739x over previous
#include <cuda_runtime.h>
#include <cuda_fp16.h>
#include <cstdint>

#define B_ 8
#define L_ 1024
#define D_ 512
#define H_ 8
#define DK_ 64
#define M_ (B_*L_)

// Scratch (no allocations allowed)
__device__ __half g_Ah[3][M_*D_];   // fp16 query/key/value
__device__ __half g_Wh[4][D_*D_];   // fp16 Wq,Wk,Wv,Wo
__device__ __half g_Q[B_*H_*L_*DK_];
__device__ __half g_K[B_*H_*L_*DK_];
__device__ __half g_V[B_*H_*L_*DK_];
__device__ __half g_X[M_*D_];
__device__ __half g_DM[B_*L_*L_];   // fp16 dist with mask folded in

// ---------------------------------------------------------------------------
// helpers
// ---------------------------------------------------------------------------
__device__ __forceinline__ uint32_t smem_to_u32(const void* p) {
    uint32_t a;
    asm("{ .reg .u64 t; cvta.to.shared.u64 t, %1; cvt.u32.u64 %0, t; }"
        : "=r"(a) : "l"(p));
    return a;
}
__device__ __forceinline__ void cp16(uint32_t dst, const void* src) {
    asm volatile("cp.async.cg.shared.global [%0], [%1], 16;"
                 :: "r"(dst), "l"(src));
}
#define CP_COMMIT asm volatile("cp.async.commit_group;")
#define CP_WAIT(n) asm volatile("cp.async.wait_group %0;" :: "n"(n))

__device__ __forceinline__ void ldsm4(uint32_t* r, uint32_t addr) {
    asm volatile("ldmatrix.sync.aligned.m8n8.x4.shared.b16 {%0,%1,%2,%3}, [%4];"
        : "=r"(r[0]), "=r"(r[1]), "=r"(r[2]), "=r"(r[3]) : "r"(addr));
}
__device__ __forceinline__ void ldsm4t(uint32_t* r, uint32_t addr) {
    asm volatile("ldmatrix.sync.aligned.m8n8.x4.trans.shared.b16 {%0,%1,%2,%3}, [%4];"
        : "=r"(r[0]), "=r"(r[1]), "=r"(r[2]), "=r"(r[3]) : "r"(addr));
}
__device__ __forceinline__ void mma_f16(float* c, const uint32_t* a, const uint32_t* b) {
    asm volatile(
        "mma.sync.aligned.m16n8k16.row.col.f32.f16.f16.f32 "
        "{%0,%1,%2,%3}, {%4,%5,%6,%7}, {%8,%9}, {%0,%1,%2,%3};"
        : "+f"(c[0]), "+f"(c[1]), "+f"(c[2]), "+f"(c[3])
        : "r"(a[0]), "r"(a[1]), "r"(a[2]), "r"(a[3]), "r"(b[0]), "r"(b[1]));
}
__device__ __forceinline__ uint32_t h2u(__half2 h) { return *(uint32_t*)&h; }
__device__ __forceinline__ float ex2(float x) {
    float r;
    asm("ex2.approx.f32 %0, %1;" : "=f"(r) : "f"(x));
    return r;
}
__device__ __forceinline__ uint32_t lds32(uint32_t addr) {
    uint32_t v;
    asm volatile("ld.shared.b32 %0, [%1];" : "=r"(v) : "r"(addr));
    return v;
}

// ===========================================================================
// fp32 -> fp16 convert pass (8 elems/thread)
// ===========================================================================
__global__ void cvt_kernel(const float4* __restrict__ s0, const float4* __restrict__ s1,
                           const float4* __restrict__ s2, const float4* __restrict__ s3,
                           uint4* d0, uint4* d1, uint4* d2, uint4* d3)
{
    const int z = blockIdx.z;
    const float4* s = (z == 0) ? s0 : (z == 1) ? s1 : (z == 2) ? s2 : s3;
    uint4* d = (z == 0) ? d0 : (z == 1) ? d1 : (z == 2) ? d2 : d3;
    const int i = blockIdx.x * blockDim.x + threadIdx.x;
    float4 u = s[2 * i], v = s[2 * i + 1];
    uint4 o;
    o.x = h2u(__floats2half2_rn(u.x, u.y));
    o.y = h2u(__floats2half2_rn(u.z, u.w));
    o.z = h2u(__floats2half2_rn(v.x, v.y));
    o.w = h2u(__floats2half2_rn(v.z, v.w));
    d[i] = o;
}

// dist + mask -> fp16 dmc (masked entries become 6e4, i.e. exp -> 0)
__global__ void cvtdist_kernel(const float4* __restrict__ dist,
                               const uchar4* __restrict__ mask,
                               uint4* __restrict__ out)
{
    const int i = blockIdx.x * blockDim.x + threadIdx.x;
    float4 a = dist[2 * i], b = dist[2 * i + 1];
    uchar4 ma = mask[2 * i], mb = mask[2 * i + 1];
    if (ma.x) a.x = 60000.f;
    if (ma.y) a.y = 60000.f;
    if (ma.z) a.z = 60000.f;
    if (ma.w) a.w = 60000.f;
    if (mb.x) b.x = 60000.f;
    if (mb.y) b.y = 60000.f;
    if (mb.z) b.z = 60000.f;
    if (mb.w) b.w = 60000.f;
    uint4 o;
    o.x = h2u(__floats2half2_rn(a.x, a.y));
    o.y = h2u(__floats2half2_rn(a.z, a.w));
    o.z = h2u(__floats2half2_rn(b.x, b.y));
    o.w = h2u(__floats2half2_rn(b.z, b.w));
    out[i] = o;
}

// ===========================================================================
// Fused projection GEMM (fp16 in, fp32 accum): C_z = A_z * W_z^T + bias_z
// Tile 128m x 64n x 64k, 3-stage cp.async, 8 warps (4m x 2n), ldmatrix frags.
// (R8 configuration — best measured)
// ===========================================================================
#define GBM 128
#define GBN 64
#define GBK 64
#define GKT (D_ / GBK)              // 8
#define GA(s) ((s) * 16384)         // A: 128 rows x 128B
#define GB(s) (49152 + (s) * 8192)  // W: 64 rows x 128B
#define GSM 73728

__global__ __launch_bounds__(256) void gemm3_kernel(
    const __half* __restrict__ A0, const __half* __restrict__ A1, const __half* __restrict__ A2,
    const __half* __restrict__ W0, const __half* __restrict__ W1, const __half* __restrict__ W2,
    const float* __restrict__ bp0, const float* __restrict__ bp1, const float* __restrict__ bp2,
    __half* __restrict__ Ch0, __half* __restrict__ Ch1, __half* __restrict__ Ch2,
    float* __restrict__ Cf, int heads)
{
    extern __shared__ char sm[];
    const uint32_t sb = smem_to_u32(sm);
    const int z = blockIdx.z;
    const __half* A    = (z == 0) ? A0 : (z == 1) ? A1 : A2;
    const __half* W    = (z == 0) ? W0 : (z == 1) ? W1 : W2;
    const float* bias  = (z == 0) ? bp0 : (z == 1) ? bp1 : bp2;
    __half* Ch         = (z == 0) ? Ch0 : (z == 1) ? Ch1 : Ch2;

    const int tid = threadIdx.x;
    const int lane = tid & 31, warp = tid >> 5;
    const int wm = warp >> 1, wn = warp & 1;
    const int g = lane >> 2, t = lane & 3;
    const int m0 = blockIdx.y * GBM, n0 = blockIdx.x * GBN;

    auto stage = [&](int kt, int s) {
        const __half* Ab = A + (size_t)m0 * D_ + kt * GBK;
#pragma unroll
        for (int i = 0; i < 4; ++i) {
            int ci = tid + 256 * i;
            int row = ci >> 3, ch = ci & 7;
            cp16(sb + GA(s) + row * 128 + ((ch ^ (row & 7)) << 4),
                 Ab + (size_t)row * D_ + ch * 8);
        }
        const __half* Wb = W + (size_t)n0 * D_ + kt * GBK;
#pragma unroll
        for (int i = 0; i < 2; ++i) {
            int ci = tid + 256 * i;
            int row = ci >> 3, ch = ci & 7;
            cp16(sb + GB(s) + row * 128 + ((ch ^ (row & 7)) << 4),
                 Wb + (size_t)row * D_ + ch * 8);
        }
        CP_COMMIT;
    };

    stage(0, 0);
    stage(1, 1);

    const int l7 = lane & 7;
    const int rowA = wm * 32 + l7 + ((lane >> 3) & 1) * 8;
    const int kchA = lane >> 4;
    const int rowB = wn * 32 + l7 + (lane >> 4) * 8;
    const int kchB = (lane >> 3) & 1;

    float acc[2][4][4] = {};

#pragma unroll 1
    for (int kt = 0; kt < GKT; ++kt) {
        if (kt < GKT - 1) { CP_WAIT(1); } else { CP_WAIT(0); }
        __syncthreads();
        if (kt + 2 < GKT) stage(kt + 2, (kt + 2) % 3);

        const uint32_t Ao = sb + GA(kt % 3), Bo = sb + GB(kt % 3);
#pragma unroll
        for (int kk = 0; kk < 4; ++kk) {
            uint32_t a[2][4], b[2][4];
#pragma unroll
            for (int mt = 0; mt < 2; ++mt)
                ldsm4(a[mt], Ao + (uint32_t)(rowA + mt * 16) * 128
                             + (((2 * kk + kchA) ^ l7) << 4));
#pragma unroll
            for (int ntp = 0; ntp < 2; ++ntp)
                ldsm4(b[ntp], Bo + (uint32_t)(rowB + ntp * 16) * 128
                              + (((2 * kk + kchB) ^ l7) << 4));
#pragma unroll
            for (int mt = 0; mt < 2; ++mt)
#pragma unroll
                for (int nt = 0; nt < 4; ++nt)
                    mma_f16(acc[mt][nt], a[mt], &b[nt >> 1][(nt & 1) * 2]);
        }
    }

    // Epilogue
#pragma unroll
    for (int mt = 0; mt < 2; ++mt) {
#pragma unroll
        for (int nt = 0; nt < 4; ++nt) {
            int n = n0 + wn * 32 + nt * 8 + 2 * t;
            float2 bv = *(const float2*)&bias[n];
            float2 r0, r1;
            r0.x = acc[mt][nt][0] + bv.x; r0.y = acc[mt][nt][1] + bv.y;
            r1.x = acc[mt][nt][2] + bv.x; r1.y = acc[mt][nt][3] + bv.y;
            int m_a = m0 + wm * 32 + mt * 16 + g;
            int m_b = m_a + 8;
            if (heads) {
                int h = n >> 6, dk = n & 63;
                int ba = m_a >> 10, la = m_a & (L_ - 1);
                int bb = m_b >> 10, lb = m_b & (L_ - 1);
                *(__half2*)&Ch[((size_t)(ba * H_ + h) * L_ + la) * DK_ + dk] =
                    __floats2half2_rn(r0.x, r0.y);
                *(__half2*)&Ch[((size_t)(bb * H_ + h) * L_ + lb) * DK_ + dk] =
                    __floats2half2_rn(r1.x, r1.y);
            } else {
                *(float2*)&Cf[(size_t)m_a * D_ + n] = r0;
                *(float2*)&Cf[(size_t)m_b * D_ + n] = r1;
            }
        }
    }
}

// ===========================================================================
// Flash attention, FA2-style: warp = 16 q-rows x ALL 64 keys (8m x 1n).
// P stays in registers (accumulator->A-fragment identity); softmax is pure
// intra-warp shfl; 2 barriers/tile. 256 threads, 128 q-rows per CTA.
// K(x2)/V(x2)/dmc(x2) cp.async buffers. log2-domain softmax (ex2.approx).
// ===========================================================================
#define AQ 0                          // 128 x 128B = 16KB
#define AK(s) (16384 + (s) * 8192)    // 2 bufs
#define AV(s) (32768 + (s) * 8192)    // 2 bufs
#define ADM(s) (49152 + (s) * 16384)  // 2 bufs (128q x 64k fp16)
#define ASMs 81920

__global__ __launch_bounds__(256, 2) void attn_kernel(
    const __half* __restrict__ Q, const __half* __restrict__ K,
    const __half* __restrict__ V, const __half* __restrict__ dmc,
    const float* __restrict__ logwb, __half* __restrict__ X)
{
    extern __shared__ char sm[];
    const uint32_t sb = smem_to_u32(sm);

    const int tid = threadIdx.x;
    const int lane = tid & 31, warp = tid >> 5;
    const int g = lane >> 2, t = lane & 3;
    const int l7 = lane & 7;
    const int bh = blockIdx.y;
    const int b = bh >> 3, h = bh & 7;
    const int q0 = blockIdx.x * 128;
    const float LOG2E = 1.4426950408889634f;
    const float wb2 = __expf(logwb[h]) * LOG2E;
    const float c1 = 0.125f * LOG2E;
    const int qr = warp * 16;                  // 0..112

    const __half* Qb = Q + (size_t)(bh * L_ + q0) * DK_;
    const __half* Kb = K + (size_t)bh * L_ * DK_;
    const __half* Vb = V + (size_t)bh * L_ * DK_;
    const __half* Db = dmc + (size_t)b * L_ * L_ + (size_t)q0 * L_;

    auto stageKVD = [&](int tile, int buf) {
        const __half* Kt = Kb + (size_t)tile * 64 * DK_;
        const __half* Vt = Vb + (size_t)tile * 64 * DK_;
        const __half* Dt = Db + tile * 64;
#pragma unroll
        for (int i = 0; i < 2; ++i) {          // K,V: 64 rows x 8 chunks
            int ci = tid + 256 * i;
            int row = ci >> 3, ch = ci & 7;
            uint32_t off = row * 128 + ((ch ^ (row & 7)) << 4);
            cp16(sb + AK(buf) + off, Kt + row * DK_ + ch * 8);
            cp16(sb + AV(buf) + off, Vt + row * DK_ + ch * 8);
        }
#pragma unroll
        for (int i = 0; i < 4; ++i) {          // dmc: 128 rows x 8 chunks
            int ci = tid + 256 * i;
            int row = ci >> 3, ch = ci & 7;
            uint32_t off = row * 128 + ((ch ^ (row & 7)) << 4);
            cp16(sb + ADM(buf) + off, Dt + (size_t)row * L_ + ch * 8);
        }
        CP_COMMIT;
    };

    // Stage Q (128 rows), then tiles 0 and 1
    {
#pragma unroll
        for (int i = 0; i < 4; ++i) {
            int ci = tid + 256 * i;
            int row = ci >> 3, ch = ci & 7;
            cp16(sb + AQ + row * 128 + ((ch ^ (row & 7)) << 4),
                 Qb + row * DK_ + ch * 8);
        }
        CP_COMMIT;
    }
    stageKVD(0, 0);
    stageKVD(1, 1);

    CP_WAIT(2);
    __syncthreads();

    // Q fragments (kept in regs whole loop)
    uint32_t qa[4][4];
#pragma unroll
    for (int kk = 0; kk < 4; ++kk)
        ldsm4(qa[kk], sb + AQ + (uint32_t)(qr + l7 + ((lane >> 3) & 1) * 8) * 128
                      + (((2 * kk + (lane >> 4)) ^ l7) << 4));

    float o[8][4] = {};
    float mrow0 = -1e30f, mrow1 = -1e30f;
    float lrow0 = 0.f, lrow1 = 0.f;

    // per-lane ldmatrix / LDS geometry
    const int keyB = l7 + (lane >> 4) * 8;     // + ntp*16 (K frags, 64 keys)
    const int kchB = (lane >> 3) & 1;
    const int keyV = l7 + ((lane >> 3) & 1) * 8;  // + kk*16 (V frags)
    const int dchV = lane >> 4;                // + ntp*2 (V d-chunks 0..7)
    const uint32_t dmr0 = (uint32_t)(qr + g) * 128 + 4 * t;
    const uint32_t dmr1 = dmr0 + 8 * 128;

#pragma unroll 1
    for (int it = 0; it < 16; ++it) {
        if (it < 15) { CP_WAIT(1); } else { CP_WAIT(0); }
        __syncthreads();                       // tile `it` staged
        const uint32_t Ko = sb + AK(it & 1), Vo = sb + AV(it & 1);
        const uint32_t Do = sb + ADM(it & 1);

        // S = Q K^T : 16q x 64k per warp
        float s[8][4] = {};
#pragma unroll
        for (int kk = 0; kk < 4; ++kk) {
            uint32_t kb[4][4];
#pragma unroll
            for (int ntp = 0; ntp < 4; ++ntp)
                ldsm4(kb[ntp], Ko + (uint32_t)(keyB + ntp * 16) * 128
                               + (((2 * kk + kchB) ^ l7) << 4));
#pragma unroll
            for (int nt = 0; nt < 8; ++nt)
                mma_f16(s[nt], qa[kk], &kb[nt >> 1][(nt & 1) * 2]);
        }

        // bias: s2 = qk*c1 - d*wb2 (log2 domain), dmc from smem
#pragma unroll
        for (int nt = 0; nt < 8; ++nt) {
            uint32_t co = (uint32_t)((nt ^ g) << 4);
            uint32_t du0 = lds32(Do + dmr0 + co);
            uint32_t du1 = lds32(Do + dmr1 + co);
            float2 d0 = __half22float2(*(__half2*)&du0);
            float2 d1 = __half22float2(*(__half2*)&du1);
            s[nt][0] = fmaf(s[nt][0], c1, -d0.x * wb2);
            s[nt][1] = fmaf(s[nt][1], c1, -d0.y * wb2);
            s[nt][2] = fmaf(s[nt][2], c1, -d1.x * wb2);
            s[nt][3] = fmaf(s[nt][3], c1, -d1.y * wb2);
        }

        // row max — fully intra-warp (warp owns all 64 keys)
        float tm0 = -1e30f, tm1 = -1e30f;
#pragma unroll
        for (int nt = 0; nt < 8; ++nt) {
            tm0 = fmaxf(tm0, fmaxf(s[nt][0], s[nt][1]));
            tm1 = fmaxf(tm1, fmaxf(s[nt][2], s[nt][3]));
        }
        tm0 = fmaxf(tm0, __shfl_xor_sync(0xffffffff, tm0, 1));
        tm0 = fmaxf(tm0, __shfl_xor_sync(0xffffffff, tm0, 2));
        tm1 = fmaxf(tm1, __shfl_xor_sync(0xffffffff, tm1, 1));
        tm1 = fmaxf(tm1, __shfl_xor_sync(0xffffffff, tm1, 2));

        float mn0 = fmaxf(mrow0, tm0);
        float mn1 = fmaxf(mrow1, tm1);
        float sc0 = ex2(mrow0 - mn0);
        float sc1 = ex2(mrow1 - mn1);
        mrow0 = mn0; mrow1 = mn1;

        // P = ex2(s - m), packed DIRECTLY into A-operand fragments (no smem)
        uint32_t pa[4][4];
        float sum0 = 0.f, sum1 = 0.f;
#pragma unroll
        for (int nt = 0; nt < 8; ++nt) {
            float p0 = ex2(s[nt][0] - mn0);
            float p1 = ex2(s[nt][1] - mn0);
            float p2 = ex2(s[nt][2] - mn1);
            float p3 = ex2(s[nt][3] - mn1);
            uint32_t lo = h2u(__floats2half2_rn(p0, p1));
            uint32_t hi = h2u(__floats2half2_rn(p2, p3));
            pa[nt >> 1][(nt & 1) * 2 + 0] = lo;
            pa[nt >> 1][(nt & 1) * 2 + 1] = hi;
            sum0 += p0 + p1;
            sum1 += p2 + p3;
        }
        sum0 += __shfl_xor_sync(0xffffffff, sum0, 1);
        sum0 += __shfl_xor_sync(0xffffffff, sum0, 2);
        sum1 += __shfl_xor_sync(0xffffffff, sum1, 1);
        sum1 += __shfl_xor_sync(0xffffffff, sum1, 2);
        lrow0 = lrow0 * sc0 + sum0;
        lrow1 = lrow1 * sc1 + sum1;

        // rescale O
#pragma unroll
        for (int nt = 0; nt < 8; ++nt) {
            o[nt][0] *= sc0; o[nt][1] *= sc0;
            o[nt][2] *= sc1; o[nt][3] *= sc1;
        }

        // O += P V : 16q x 64d per warp
#pragma unroll
        for (int kk = 0; kk < 4; ++kk) {
            uint32_t vb[4][4];
#pragma unroll
            for (int ntp = 0; ntp < 4; ++ntp)
                ldsm4t(vb[ntp], Vo + (uint32_t)(kk * 16 + keyV) * 128
                                + (((ntp * 2 + dchV) ^ l7) << 4));
#pragma unroll
            for (int nt = 0; nt < 8; ++nt)
                mma_f16(o[nt], pa[kk], &vb[nt >> 1][(nt & 1) * 2]);
        }

        __syncthreads();                       // all warps done with tile `it`
        if (it + 2 < 16) stageKVD(it + 2, it & 1);
    }

    // Normalize, write X (fp16) in (B, L, D)
    float inv0 = 1.f / lrow0;
    float inv1 = 1.f / lrow1;
    const size_t xr0 = (size_t)(b * L_ + q0 + qr + g) * D_ + h * DK_;
    const size_t xr1 = xr0 + 8 * D_;
#pragma unroll
    for (int nt = 0; nt < 8; ++nt) {
        int c = nt * 8 + 2 * t;
        *(__half2*)&X[xr0 + c] = __floats2half2_rn(o[nt][0] * inv0, o[nt][1] * inv0);
        *(__half2*)&X[xr1 + c] = __floats2half2_rn(o[nt][2] * inv1, o[nt][3] * inv1);
    }
}

// ---------------------------------------------------------------------------
extern "C" void kernel_launch(void* const* d_in, const int* in_sizes, int n_in,
                              void* d_out, int out_size)
{
    const float* query = (const float*)d_in[0];
    const float* key_  = (const float*)d_in[1];
    const float* value = (const float*)d_in[2];
    const float* dist  = (const float*)d_in[3];
    const unsigned char* mask = (const unsigned char*)d_in[4];
    const float* Wq = (const float*)d_in[5];
    const float* bq = (const float*)d_in[6];
    const float* Wk = (const float*)d_in[7];
    const float* bk = (const float*)d_in[8];
    const float* Wv = (const float*)d_in[9];
    const float* bv = (const float*)d_in[10];
    const float* Wo = (const float*)d_in[11];
    const float* bo = (const float*)d_in[12];
    const float* logwb = (const float*)d_in[13];

    __half *Ah, *Wh, *Qp, *Kp, *Vp, *Xp, *Dp;
    cudaGetSymbolAddress((void**)&Ah, g_Ah);
    cudaGetSymbolAddress((void**)&Wh, g_Wh);
    cudaGetSymbolAddress((void**)&Qp, g_Q);
    cudaGetSymbolAddress((void**)&Kp, g_K);
    cudaGetSymbolAddress((void**)&Vp, g_V);
    cudaGetSymbolAddress((void**)&Xp, g_X);
    cudaGetSymbolAddress((void**)&Dp, g_DM);
    __half* A0 = Ah;            __half* A1 = Ah + (size_t)M_ * D_;
    __half* A2 = Ah + 2 * (size_t)M_ * D_;
    __half* W0 = Wh;            __half* W1 = Wh + (size_t)D_ * D_;
    __half* W2 = Wh + 2 * (size_t)D_ * D_;
    __half* W3 = Wh + 3 * (size_t)D_ * D_;

    cudaFuncSetAttribute(gemm3_kernel,
                         cudaFuncAttributeMaxDynamicSharedMemorySize, GSM);
    cudaFuncSetAttribute(attn_kernel,
                         cudaFuncAttributeMaxDynamicSharedMemorySize, ASMs);

    // fp32 -> fp16 conversion passes
    cvt_kernel<<<dim3(M_ * D_ / (8 * 256), 1, 3), 256>>>(
        (const float4*)query, (const float4*)key_, (const float4*)value,
        (const float4*)query,
        (uint4*)A0, (uint4*)A1, (uint4*)A2, (uint4*)A0);
    cvt_kernel<<<dim3(D_ * D_ / (8 * 256), 1, 4), 256>>>(
        (const float4*)Wq, (const float4*)Wk, (const float4*)Wv, (const float4*)Wo,
        (uint4*)W0, (uint4*)W1, (uint4*)W2, (uint4*)W3);
    cvtdist_kernel<<<B_ * L_ * L_ / (8 * 256), 256>>>(
        (const float4*)dist, (const uchar4*)mask, (uint4*)Dp);

    // Fused Q/K/V projections
    gemm3_kernel<<<dim3(D_ / GBN, M_ / GBM, 3), 256, GSM>>>(
        A0, A1, A2, W0, W1, W2, bq, bk, bv, Qp, Kp, Vp, nullptr, 1);

    attn_kernel<<<dim3(L_ / 128, B_ * H_), 256, ASMs>>>(
        Qp, Kp, Vp, Dp, logwb, Xp);

    // Output projection (fp32 out)
    gemm3_kernel<<<dim3(D_ / GBN, M_ / GBM, 1), 256, GSM>>>(
        Xp, Xp, Xp, W3, W3, W3, bo, bo, bo,
        nullptr, nullptr, nullptr, (float*)d_out, 0);
}

// round 12
// speedup vs baseline: 1.3012x; 1.0215x over previous
#include <cuda_runtime.h>
#include <cuda_fp16.h>
#include <cstdint>

#define B_ 8
#define L_ 1024
#define D_ 512
#define H_ 8
#define DK_ 64
#define M_ (B_*L_)

// Scratch (no allocations allowed)
__device__ __half g_Ah[3][M_*D_];   // fp16 query/key/value
__device__ __half g_Wh[4][D_*D_];   // fp16 Wq,Wk,Wv,Wo
__device__ __half g_Q[B_*H_*L_*DK_];
__device__ __half g_K[B_*H_*L_*DK_];
__device__ __half g_V[B_*H_*L_*DK_];
__device__ __half g_X[M_*D_];
__device__ __half g_DM[B_*L_*L_];   // fp16 dist with mask folded in

// ---------------------------------------------------------------------------
// helpers
// ---------------------------------------------------------------------------
__device__ __forceinline__ uint32_t smem_to_u32(const void* p) {
    uint32_t a;
    asm("{ .reg .u64 t; cvta.to.shared.u64 t, %1; cvt.u32.u64 %0, t; }"
        : "=r"(a) : "l"(p));
    return a;
}
__device__ __forceinline__ void cp16(uint32_t dst, const void* src) {
    asm volatile("cp.async.cg.shared.global [%0], [%1], 16;"
                 :: "r"(dst), "l"(src));
}
#define CP_COMMIT asm volatile("cp.async.commit_group;")
#define CP_WAIT(n) asm volatile("cp.async.wait_group %0;" :: "n"(n))

__device__ __forceinline__ void ldsm4(uint32_t* r, uint32_t addr) {
    asm volatile("ldmatrix.sync.aligned.m8n8.x4.shared.b16 {%0,%1,%2,%3}, [%4];"
        : "=r"(r[0]), "=r"(r[1]), "=r"(r[2]), "=r"(r[3]) : "r"(addr));
}
__device__ __forceinline__ void ldsm4t(uint32_t* r, uint32_t addr) {
    asm volatile("ldmatrix.sync.aligned.m8n8.x4.trans.shared.b16 {%0,%1,%2,%3}, [%4];"
        : "=r"(r[0]), "=r"(r[1]), "=r"(r[2]), "=r"(r[3]) : "r"(addr));
}
__device__ __forceinline__ void mma_f16(float* c, const uint32_t* a, const uint32_t* b) {
    asm volatile(
        "mma.sync.aligned.m16n8k16.row.col.f32.f16.f16.f32 "
        "{%0,%1,%2,%3}, {%4,%5,%6,%7}, {%8,%9}, {%0,%1,%2,%3};"
        : "+f"(c[0]), "+f"(c[1]), "+f"(c[2]), "+f"(c[3])
        : "r"(a[0]), "r"(a[1]), "r"(a[2]), "r"(a[3]), "r"(b[0]), "r"(b[1]));
}
__device__ __forceinline__ uint32_t h2u(__half2 h) { return *(uint32_t*)&h; }
__device__ __forceinline__ float ex2(float x) {
    float r;
    asm("ex2.approx.f32 %0, %1;" : "=f"(r) : "f"(x));
    return r;
}
__device__ __forceinline__ uint32_t lds32(uint32_t addr) {
    uint32_t v;
    asm volatile("ld.shared.b32 %0, [%1];" : "=r"(v) : "r"(addr));
    return v;
}

// ===========================================================================
// One fused prep pass: fp32->fp16 for inputs (3) + weights (4), and
// dist+mask -> fp16 dmc. Block ranges: [0,6144) inputs, [6144,6656) weights,
// [6656,10752) dist. Each block: 2048 elems (256 thr x 8).
// ===========================================================================
#define PREP_BLOCKS 10752

__global__ __launch_bounds__(256) void prep_kernel(
    const float* __restrict__ query, const float* __restrict__ key_,
    const float* __restrict__ value,
    const float* __restrict__ Wq, const float* __restrict__ Wk,
    const float* __restrict__ Wv, const float* __restrict__ Wo,
    const float* __restrict__ dist, const unsigned char* __restrict__ mask,
    __half* __restrict__ Ah, __half* __restrict__ Wh, __half* __restrict__ DM)
{
    const int bid = blockIdx.x;
    const int tid = threadIdx.x;
    if (bid < 6144) {
        const int z = bid >> 11;                 // /2048
        const float4* s = (const float4*)((z == 0) ? query : (z == 1) ? key_ : value);
        uint4* d = (uint4*)(Ah + (size_t)z * M_ * D_);
        const int i = (bid - z * 2048) * 256 + tid;
        float4 u = s[2 * i], v = s[2 * i + 1];
        uint4 o;
        o.x = h2u(__floats2half2_rn(u.x, u.y));
        o.y = h2u(__floats2half2_rn(u.z, u.w));
        o.z = h2u(__floats2half2_rn(v.x, v.y));
        o.w = h2u(__floats2half2_rn(v.z, v.w));
        d[i] = o;
    } else if (bid < 6656) {
        const int r = bid - 6144;
        const int z = r >> 7;                    // /128
        const float4* s = (const float4*)((z == 0) ? Wq : (z == 1) ? Wk : (z == 2) ? Wv : Wo);
        uint4* d = (uint4*)(Wh + (size_t)z * D_ * D_);
        const int i = (r - z * 128) * 256 + tid;
        float4 u = s[2 * i], v = s[2 * i + 1];
        uint4 o;
        o.x = h2u(__floats2half2_rn(u.x, u.y));
        o.y = h2u(__floats2half2_rn(u.z, u.w));
        o.z = h2u(__floats2half2_rn(v.x, v.y));
        o.w = h2u(__floats2half2_rn(v.z, v.w));
        d[i] = o;
    } else {
        const int i = (bid - 6656) * 256 + tid;
        float4 a = ((const float4*)dist)[2 * i];
        float4 b = ((const float4*)dist)[2 * i + 1];
        uchar4 ma = ((const uchar4*)mask)[2 * i];
        uchar4 mb = ((const uchar4*)mask)[2 * i + 1];
        if (ma.x) a.x = 60000.f;
        if (ma.y) a.y = 60000.f;
        if (ma.z) a.z = 60000.f;
        if (ma.w) a.w = 60000.f;
        if (mb.x) b.x = 60000.f;
        if (mb.y) b.y = 60000.f;
        if (mb.z) b.z = 60000.f;
        if (mb.w) b.w = 60000.f;
        uint4 o;
        o.x = h2u(__floats2half2_rn(a.x, a.y));
        o.y = h2u(__floats2half2_rn(a.z, a.w));
        o.z = h2u(__floats2half2_rn(b.x, b.y));
        o.w = h2u(__floats2half2_rn(b.z, b.w));
        ((uint4*)DM)[i] = o;
    }
}

// ===========================================================================
// Fused projection GEMM (fp16 in, fp32 accum): C_z = A_z * W_z^T + bias_z
// Tile 128m x 64n x 64k, 3-stage cp.async, 8 warps (4m x 2n), ldmatrix frags.
// (R8 configuration — best measured)
// ===========================================================================
#define GBM 128
#define GBN 64
#define GBK 64
#define GKT (D_ / GBK)              // 8
#define GA(s) ((s) * 16384)         // A: 128 rows x 128B
#define GB(s) (49152 + (s) * 8192)  // W: 64 rows x 128B
#define GSM 73728

__global__ __launch_bounds__(256) void gemm3_kernel(
    const __half* __restrict__ A0, const __half* __restrict__ A1, const __half* __restrict__ A2,
    const __half* __restrict__ W0, const __half* __restrict__ W1, const __half* __restrict__ W2,
    const float* __restrict__ bp0, const float* __restrict__ bp1, const float* __restrict__ bp2,
    __half* __restrict__ Ch0, __half* __restrict__ Ch1, __half* __restrict__ Ch2,
    float* __restrict__ Cf, int heads)
{
    extern __shared__ char sm[];
    const uint32_t sb = smem_to_u32(sm);
    const int z = blockIdx.z;
    const __half* A    = (z == 0) ? A0 : (z == 1) ? A1 : A2;
    const __half* W    = (z == 0) ? W0 : (z == 1) ? W1 : W2;
    const float* bias  = (z == 0) ? bp0 : (z == 1) ? bp1 : bp2;
    __half* Ch         = (z == 0) ? Ch0 : (z == 1) ? Ch1 : Ch2;

    const int tid = threadIdx.x;
    const int lane = tid & 31, warp = tid >> 5;
    const int wm = warp >> 1, wn = warp & 1;
    const int g = lane >> 2, t = lane & 3;
    const int m0 = blockIdx.y * GBM, n0 = blockIdx.x * GBN;

    auto stage = [&](int kt, int s) {
        const __half* Ab = A + (size_t)m0 * D_ + kt * GBK;
#pragma unroll
        for (int i = 0; i < 4; ++i) {
            int ci = tid + 256 * i;
            int row = ci >> 3, ch = ci & 7;
            cp16(sb + GA(s) + row * 128 + ((ch ^ (row & 7)) << 4),
                 Ab + (size_t)row * D_ + ch * 8);
        }
        const __half* Wb = W + (size_t)n0 * D_ + kt * GBK;
#pragma unroll
        for (int i = 0; i < 2; ++i) {
            int ci = tid + 256 * i;
            int row = ci >> 3, ch = ci & 7;
            cp16(sb + GB(s) + row * 128 + ((ch ^ (row & 7)) << 4),
                 Wb + (size_t)row * D_ + ch * 8);
        }
        CP_COMMIT;
    };

    stage(0, 0);
    stage(1, 1);

    const int l7 = lane & 7;
    const int rowA = wm * 32 + l7 + ((lane >> 3) & 1) * 8;
    const int kchA = lane >> 4;
    const int rowB = wn * 32 + l7 + (lane >> 4) * 8;
    const int kchB = (lane >> 3) & 1;

    float acc[2][4][4] = {};

#pragma unroll 1
    for (int kt = 0; kt < GKT; ++kt) {
        if (kt < GKT - 1) { CP_WAIT(1); } else { CP_WAIT(0); }
        __syncthreads();
        if (kt + 2 < GKT) stage(kt + 2, (kt + 2) % 3);

        const uint32_t Ao = sb + GA(kt % 3), Bo = sb + GB(kt % 3);
#pragma unroll
        for (int kk = 0; kk < 4; ++kk) {
            uint32_t a[2][4], b[2][4];
#pragma unroll
            for (int mt = 0; mt < 2; ++mt)
                ldsm4(a[mt], Ao + (uint32_t)(rowA + mt * 16) * 128
                             + (((2 * kk + kchA) ^ l7) << 4));
#pragma unroll
            for (int ntp = 0; ntp < 2; ++ntp)
                ldsm4(b[ntp], Bo + (uint32_t)(rowB + ntp * 16) * 128
                              + (((2 * kk + kchB) ^ l7) << 4));
#pragma unroll
            for (int mt = 0; mt < 2; ++mt)
#pragma unroll
                for (int nt = 0; nt < 4; ++nt)
                    mma_f16(acc[mt][nt], a[mt], &b[nt >> 1][(nt & 1) * 2]);
        }
    }

    // Epilogue
#pragma unroll
    for (int mt = 0; mt < 2; ++mt) {
#pragma unroll
        for (int nt = 0; nt < 4; ++nt) {
            int n = n0 + wn * 32 + nt * 8 + 2 * t;
            float2 bv = *(const float2*)&bias[n];
            float2 r0, r1;
            r0.x = acc[mt][nt][0] + bv.x; r0.y = acc[mt][nt][1] + bv.y;
            r1.x = acc[mt][nt][2] + bv.x; r1.y = acc[mt][nt][3] + bv.y;
            int m_a = m0 + wm * 32 + mt * 16 + g;
            int m_b = m_a + 8;
            if (heads) {
                int h = n >> 6, dk = n & 63;
                int ba = m_a >> 10, la = m_a & (L_ - 1);
                int bb = m_b >> 10, lb = m_b & (L_ - 1);
                *(__half2*)&Ch[((size_t)(ba * H_ + h) * L_ + la) * DK_ + dk] =
                    __floats2half2_rn(r0.x, r0.y);
                *(__half2*)&Ch[((size_t)(bb * H_ + h) * L_ + lb) * DK_ + dk] =
                    __floats2half2_rn(r1.x, r1.y);
            } else {
                *(float2*)&Cf[(size_t)m_a * D_ + n] = r0;
                *(float2*)&Cf[(size_t)m_b * D_ + n] = r1;
            }
        }
    }
}

// ===========================================================================
// Flash attention, FA2-style: warp = 16 q-rows x ALL 64 keys (8m x 1n).
// P stays in registers; softmax pure intra-warp shfl; ONE barrier per tile
// (3-deep K/V/dmc cp.async ring makes the trailing barrier unnecessary).
// 256 threads, 128 q-rows per CTA. log2-domain softmax (ex2.approx).
// ===========================================================================
#define AQ 0                          // 128 x 128B = 16KB
#define AK(s) (16384 + (s) * 8192)    // 3 bufs
#define AV(s) (40960 + (s) * 8192)    // 3 bufs
#define ADM(s) (65536 + (s) * 16384)  // 3 bufs (128q x 64k fp16)
#define ASMs 114688                   // 112KB -> 2 CTAs/SM (224KB)

__global__ __launch_bounds__(256, 2) void attn_kernel(
    const __half* __restrict__ Q, const __half* __restrict__ K,
    const __half* __restrict__ V, const __half* __restrict__ dmc,
    const float* __restrict__ logwb, __half* __restrict__ X)
{
    extern __shared__ char sm[];
    const uint32_t sb = smem_to_u32(sm);

    const int tid = threadIdx.x;
    const int lane = tid & 31, warp = tid >> 5;
    const int g = lane >> 2, t = lane & 3;
    const int l7 = lane & 7;
    const int bh = blockIdx.y;
    const int b = bh >> 3, h = bh & 7;
    const int q0 = blockIdx.x * 128;
    const float LOG2E = 1.4426950408889634f;
    const float wb2 = __expf(logwb[h]) * LOG2E;
    const float c1 = 0.125f * LOG2E;
    const int qr = warp * 16;                  // 0..112

    const __half* Qb = Q + (size_t)(bh * L_ + q0) * DK_;
    const __half* Kb = K + (size_t)bh * L_ * DK_;
    const __half* Vb = V + (size_t)bh * L_ * DK_;
    const __half* Db = dmc + (size_t)b * L_ * L_ + (size_t)q0 * L_;

    auto stageKVD = [&](int tile, int buf) {
        const __half* Kt = Kb + (size_t)tile * 64 * DK_;
        const __half* Vt = Vb + (size_t)tile * 64 * DK_;
        const __half* Dt = Db + tile * 64;
#pragma unroll
        for (int i = 0; i < 2; ++i) {          // K,V: 64 rows x 8 chunks
            int ci = tid + 256 * i;
            int row = ci >> 3, ch = ci & 7;
            uint32_t off = row * 128 + ((ch ^ (row & 7)) << 4);
            cp16(sb + AK(buf) + off, Kt + row * DK_ + ch * 8);
            cp16(sb + AV(buf) + off, Vt + row * DK_ + ch * 8);
        }
#pragma unroll
        for (int i = 0; i < 4; ++i) {          // dmc: 128 rows x 8 chunks
            int ci = tid + 256 * i;
            int row = ci >> 3, ch = ci & 7;
            uint32_t off = row * 128 + ((ch ^ (row & 7)) << 4);
            cp16(sb + ADM(buf) + off, Dt + (size_t)row * L_ + ch * 8);
        }
        CP_COMMIT;
    };

    // Stage Q (128 rows), then tiles 0 and 1
    {
#pragma unroll
        for (int i = 0; i < 4; ++i) {
            int ci = tid + 256 * i;
            int row = ci >> 3, ch = ci & 7;
            cp16(sb + AQ + row * 128 + ((ch ^ (row & 7)) << 4),
                 Qb + row * DK_ + ch * 8);
        }
        CP_COMMIT;
    }
    stageKVD(0, 0);
    stageKVD(1, 1);

    CP_WAIT(2);
    __syncthreads();

    // Q fragments (kept in regs whole loop)
    uint32_t qa[4][4];
#pragma unroll
    for (int kk = 0; kk < 4; ++kk)
        ldsm4(qa[kk], sb + AQ + (uint32_t)(qr + l7 + ((lane >> 3) & 1) * 8) * 128
                      + (((2 * kk + (lane >> 4)) ^ l7) << 4));

    float o[8][4] = {};
    float mrow0 = -1e30f, mrow1 = -1e30f;
    float lrow0 = 0.f, lrow1 = 0.f;

    // per-lane ldmatrix / LDS geometry
    const int keyB = l7 + (lane >> 4) * 8;     // + ntp*16 (K frags, 64 keys)
    const int kchB = (lane >> 3) & 1;
    const int keyV = l7 + ((lane >> 3) & 1) * 8;  // + kk*16 (V frags)
    const int dchV = lane >> 4;                // + ntp*2 (V d-chunks 0..7)
    const uint32_t dmr0 = (uint32_t)(qr + g) * 128 + 4 * t;
    const uint32_t dmr1 = dmr0 + 8 * 128;

#pragma unroll 1
    for (int it = 0; it < 16; ++it) {
        if (it < 15) { CP_WAIT(1); } else { CP_WAIT(0); }
        __syncthreads();                       // tile `it` staged; buf (it-1)%3 free
        if (it + 2 < 16) stageKVD(it + 2, (it + 2) % 3);

        const uint32_t Ko = sb + AK(it % 3), Vo = sb + AV(it % 3);
        const uint32_t Do = sb + ADM(it % 3);

        // S = Q K^T : 16q x 64k per warp
        float s[8][4] = {};
#pragma unroll
        for (int kk = 0; kk < 4; ++kk) {
            uint32_t kb[4][4];
#pragma unroll
            for (int ntp = 0; ntp < 4; ++ntp)
                ldsm4(kb[ntp], Ko + (uint32_t)(keyB + ntp * 16) * 128
                               + (((2 * kk + kchB) ^ l7) << 4));
#pragma unroll
            for (int nt = 0; nt < 8; ++nt)
                mma_f16(s[nt], qa[kk], &kb[nt >> 1][(nt & 1) * 2]);
        }

        // bias: s2 = qk*c1 - d*wb2 (log2 domain), dmc from smem
#pragma unroll
        for (int nt = 0; nt < 8; ++nt) {
            uint32_t co = (uint32_t)((nt ^ g) << 4);
            uint32_t du0 = lds32(Do + dmr0 + co);
            uint32_t du1 = lds32(Do + dmr1 + co);
            float2 d0 = __half22float2(*(__half2*)&du0);
            float2 d1 = __half22float2(*(__half2*)&du1);
            s[nt][0] = fmaf(s[nt][0], c1, -d0.x * wb2);
            s[nt][1] = fmaf(s[nt][1], c1, -d0.y * wb2);
            s[nt][2] = fmaf(s[nt][2], c1, -d1.x * wb2);
            s[nt][3] = fmaf(s[nt][3], c1, -d1.y * wb2);
        }

        // row max — fully intra-warp (warp owns all 64 keys)
        float tm0 = -1e30f, tm1 = -1e30f;
#pragma unroll
        for (int nt = 0; nt < 8; ++nt) {
            tm0 = fmaxf(tm0, fmaxf(s[nt][0], s[nt][1]));
            tm1 = fmaxf(tm1, fmaxf(s[nt][2], s[nt][3]));
        }
        tm0 = fmaxf(tm0, __shfl_xor_sync(0xffffffff, tm0, 1));
        tm0 = fmaxf(tm0, __shfl_xor_sync(0xffffffff, tm0, 2));
        tm1 = fmaxf(tm1, __shfl_xor_sync(0xffffffff, tm1, 1));
        tm1 = fmaxf(tm1, __shfl_xor_sync(0xffffffff, tm1, 2));

        float mn0 = fmaxf(mrow0, tm0);
        float mn1 = fmaxf(mrow1, tm1);
        float sc0 = ex2(mrow0 - mn0);
        float sc1 = ex2(mrow1 - mn1);
        mrow0 = mn0; mrow1 = mn1;

        // P = ex2(s - m), packed DIRECTLY into A-operand fragments (no smem)
        uint32_t pa[4][4];
        float sum0 = 0.f, sum1 = 0.f;
#pragma unroll
        for (int nt = 0; nt < 8; ++nt) {
            float p0 = ex2(s[nt][0] - mn0);
            float p1 = ex2(s[nt][1] - mn0);
            float p2 = ex2(s[nt][2] - mn1);
            float p3 = ex2(s[nt][3] - mn1);
            uint32_t lo = h2u(__floats2half2_rn(p0, p1));
            uint32_t hi = h2u(__floats2half2_rn(p2, p3));
            pa[nt >> 1][(nt & 1) * 2 + 0] = lo;
            pa[nt >> 1][(nt & 1) * 2 + 1] = hi;
            sum0 += p0 + p1;
            sum1 += p2 + p3;
        }
        sum0 += __shfl_xor_sync(0xffffffff, sum0, 1);
        sum0 += __shfl_xor_sync(0xffffffff, sum0, 2);
        sum1 += __shfl_xor_sync(0xffffffff, sum1, 1);
        sum1 += __shfl_xor_sync(0xffffffff, sum1, 2);
        lrow0 = lrow0 * sc0 + sum0;
        lrow1 = lrow1 * sc1 + sum1;

        // rescale O
#pragma unroll
        for (int nt = 0; nt < 8; ++nt) {
            o[nt][0] *= sc0; o[nt][1] *= sc0;
            o[nt][2] *= sc1; o[nt][3] *= sc1;
        }

        // O += P V : 16q x 64d per warp
#pragma unroll
        for (int kk = 0; kk < 4; ++kk) {
            uint32_t vb[4][4];
#pragma unroll
            for (int ntp = 0; ntp < 4; ++ntp)
                ldsm4t(vb[ntp], Vo + (uint32_t)(kk * 16 + keyV) * 128
                                + (((ntp * 2 + dchV) ^ l7) << 4));
#pragma unroll
            for (int nt = 0; nt < 8; ++nt)
                mma_f16(o[nt], pa[kk], &vb[nt >> 1][(nt & 1) * 2]);
        }
        // no trailing barrier: next iteration's sync covers buffer reuse
    }

    // Normalize, write X (fp16) in (B, L, D)
    float inv0 = 1.f / lrow0;
    float inv1 = 1.f / lrow1;
    const size_t xr0 = (size_t)(b * L_ + q0 + qr + g) * D_ + h * DK_;
    const size_t xr1 = xr0 + 8 * D_;
#pragma unroll
    for (int nt = 0; nt < 8; ++nt) {
        int c = nt * 8 + 2 * t;
        *(__half2*)&X[xr0 + c] = __floats2half2_rn(o[nt][0] * inv0, o[nt][1] * inv0);
        *(__half2*)&X[xr1 + c] = __floats2half2_rn(o[nt][2] * inv1, o[nt][3] * inv1);
    }
}

// ---------------------------------------------------------------------------
extern "C" void kernel_launch(void* const* d_in, const int* in_sizes, int n_in,
                              void* d_out, int out_size)
{
    const float* query = (const float*)d_in[0];
    const float* key_  = (const float*)d_in[1];
    const float* value = (const float*)d_in[2];
    const float* dist  = (const float*)d_in[3];
    const unsigned char* mask = (const unsigned char*)d_in[4];
    const float* Wq = (const float*)d_in[5];
    const float* bq = (const float*)d_in[6];
    const float* Wk = (const float*)d_in[7];
    const float* bk = (const float*)d_in[8];
    const float* Wv = (const float*)d_in[9];
    const float* bv = (const float*)d_in[10];
    const float* Wo = (const float*)d_in[11];
    const float* bo = (const float*)d_in[12];
    const float* logwb = (const float*)d_in[13];

    __half *Ah, *Wh, *Qp, *Kp, *Vp, *Xp, *Dp;
    cudaGetSymbolAddress((void**)&Ah, g_Ah);
    cudaGetSymbolAddress((void**)&Wh, g_Wh);
    cudaGetSymbolAddress((void**)&Qp, g_Q);
    cudaGetSymbolAddress((void**)&Kp, g_K);
    cudaGetSymbolAddress((void**)&Vp, g_V);
    cudaGetSymbolAddress((void**)&Xp, g_X);
    cudaGetSymbolAddress((void**)&Dp, g_DM);
    __half* A0 = Ah;            __half* A1 = Ah + (size_t)M_ * D_;
    __half* A2 = Ah + 2 * (size_t)M_ * D_;
    __half* W0 = Wh;            __half* W1 = Wh + (size_t)D_ * D_;
    __half* W2 = Wh + 2 * (size_t)D_ * D_;
    __half* W3 = Wh + 3 * (size_t)D_ * D_;

    cudaFuncSetAttribute(gemm3_kernel,
                         cudaFuncAttributeMaxDynamicSharedMemorySize, GSM);
    cudaFuncSetAttribute(attn_kernel,
                         cudaFuncAttributeMaxDynamicSharedMemorySize, ASMs);

    // One fused prep pass (input/weight fp16 conversion + dist/mask fold)
    prep_kernel<<<PREP_BLOCKS, 256>>>(
        query, key_, value, Wq, Wk, Wv, Wo, dist, mask, Ah, Wh, Dp);

    // Fused Q/K/V projections
    gemm3_kernel<<<dim3(D_ / GBN, M_ / GBM, 3), 256, GSM>>>(
        A0, A1, A2, W0, W1, W2, bq, bk, bv, Qp, Kp, Vp, nullptr, 1);

    attn_kernel<<<dim3(L_ / 128, B_ * H_), 256, ASMs>>>(
        Qp, Kp, Vp, Dp, logwb, Xp);

    // Output projection (fp32 out)
    gemm3_kernel<<<dim3(D_ / GBN, M_ / GBM, 1), 256, GSM>>>(
        Xp, Xp, Xp, W3, W3, W3, bo, bo, bo,
        nullptr, nullptr, nullptr, (float*)d_out, 0);
}

// round 13
// speedup vs baseline: 1.3619x; 1.0466x over previous
#include <cuda_runtime.h>
#include <cuda_fp16.h>
#include <cstdint>

#define B_ 8
#define L_ 1024
#define D_ 512
#define H_ 8
#define DK_ 64
#define M_ (B_*L_)

// Scratch (no allocations allowed)
__device__ __half g_Ah[3][M_*D_];   // fp16 query/key/value
__device__ __half g_Wh[4][D_*D_];   // fp16 Wq,Wk,Wv,Wo
__device__ __half g_Q[B_*H_*L_*DK_];
__device__ __half g_K[B_*H_*L_*DK_];
__device__ __half g_V[B_*H_*L_*DK_];
__device__ __half g_X[M_*D_];
__device__ __half g_DM[B_*L_*L_];   // fp16 dist with mask folded in

// ---------------------------------------------------------------------------
// helpers
// ---------------------------------------------------------------------------
__device__ __forceinline__ uint32_t smem_to_u32(const void* p) {
    uint32_t a;
    asm("{ .reg .u64 t; cvta.to.shared.u64 t, %1; cvt.u32.u64 %0, t; }"
        : "=r"(a) : "l"(p));
    return a;
}
__device__ __forceinline__ void cp16(uint32_t dst, const void* src) {
    asm volatile("cp.async.cg.shared.global [%0], [%1], 16;"
                 :: "r"(dst), "l"(src));
}
#define CP_COMMIT asm volatile("cp.async.commit_group;")
#define CP_WAIT(n) asm volatile("cp.async.wait_group %0;" :: "n"(n))

__device__ __forceinline__ void ldsm4(uint32_t* r, uint32_t addr) {
    asm volatile("ldmatrix.sync.aligned.m8n8.x4.shared.b16 {%0,%1,%2,%3}, [%4];"
        : "=r"(r[0]), "=r"(r[1]), "=r"(r[2]), "=r"(r[3]) : "r"(addr));
}
__device__ __forceinline__ void ldsm4t(uint32_t* r, uint32_t addr) {
    asm volatile("ldmatrix.sync.aligned.m8n8.x4.trans.shared.b16 {%0,%1,%2,%3}, [%4];"
        : "=r"(r[0]), "=r"(r[1]), "=r"(r[2]), "=r"(r[3]) : "r"(addr));
}
__device__ __forceinline__ void mma_f16(float* c, const uint32_t* a, const uint32_t* b) {
    asm volatile(
        "mma.sync.aligned.m16n8k16.row.col.f32.f16.f16.f32 "
        "{%0,%1,%2,%3}, {%4,%5,%6,%7}, {%8,%9}, {%0,%1,%2,%3};"
        : "+f"(c[0]), "+f"(c[1]), "+f"(c[2]), "+f"(c[3])
        : "r"(a[0]), "r"(a[1]), "r"(a[2]), "r"(a[3]), "r"(b[0]), "r"(b[1]));
}
__device__ __forceinline__ uint32_t h2u(__half2 h) { return *(uint32_t*)&h; }
__device__ __forceinline__ float ex2(float x) {
    float r;
    asm("ex2.approx.f32 %0, %1;" : "=f"(r) : "f"(x));
    return r;
}
__device__ __forceinline__ uint32_t ex2_h2(uint32_t x) {
    uint32_t r;
    asm("ex2.approx.f16x2 %0, %1;" : "=r"(r) : "r"(x));
    return r;
}

// ===========================================================================
// One fused prep pass: fp32->fp16 for inputs (3) + weights (4), and
// dist+mask -> fp16 dmc. Block ranges: [0,6144) inputs, [6144,6656) weights,
// [6656,10752) dist. Each block: 2048 elems (256 thr x 8).
// ===========================================================================
#define PREP_BLOCKS 10752

__global__ __launch_bounds__(256) void prep_kernel(
    const float* __restrict__ query, const float* __restrict__ key_,
    const float* __restrict__ value,
    const float* __restrict__ Wq, const float* __restrict__ Wk,
    const float* __restrict__ Wv, const float* __restrict__ Wo,
    const float* __restrict__ dist, const unsigned char* __restrict__ mask,
    __half* __restrict__ Ah, __half* __restrict__ Wh, __half* __restrict__ DM)
{
    const int bid = blockIdx.x;
    const int tid = threadIdx.x;
    if (bid < 6144) {
        const int z = bid >> 11;
        const float4* s = (const float4*)((z == 0) ? query : (z == 1) ? key_ : value);
        uint4* d = (uint4*)(Ah + (size_t)z * M_ * D_);
        const int i = (bid - z * 2048) * 256 + tid;
        float4 u = s[2 * i], v = s[2 * i + 1];
        uint4 o;
        o.x = h2u(__floats2half2_rn(u.x, u.y));
        o.y = h2u(__floats2half2_rn(u.z, u.w));
        o.z = h2u(__floats2half2_rn(v.x, v.y));
        o.w = h2u(__floats2half2_rn(v.z, v.w));
        d[i] = o;
    } else if (bid < 6656) {
        const int r = bid - 6144;
        const int z = r >> 7;
        const float4* s = (const float4*)((z == 0) ? Wq : (z == 1) ? Wk : (z == 2) ? Wv : Wo);
        uint4* d = (uint4*)(Wh + (size_t)z * D_ * D_);
        const int i = (r - z * 128) * 256 + tid;
        float4 u = s[2 * i], v = s[2 * i + 1];
        uint4 o;
        o.x = h2u(__floats2half2_rn(u.x, u.y));
        o.y = h2u(__floats2half2_rn(u.z, u.w));
        o.z = h2u(__floats2half2_rn(v.x, v.y));
        o.w = h2u(__floats2half2_rn(v.z, v.w));
        d[i] = o;
    } else {
        const int i = (bid - 6656) * 256 + tid;
        float4 a = ((const float4*)dist)[2 * i];
        float4 b = ((const float4*)dist)[2 * i + 1];
        uchar4 ma = ((const uchar4*)mask)[2 * i];
        uchar4 mb = ((const uchar4*)mask)[2 * i + 1];
        if (ma.x) a.x = 60000.f;
        if (ma.y) a.y = 60000.f;
        if (ma.z) a.z = 60000.f;
        if (ma.w) a.w = 60000.f;
        if (mb.x) b.x = 60000.f;
        if (mb.y) b.y = 60000.f;
        if (mb.z) b.z = 60000.f;
        if (mb.w) b.w = 60000.f;
        uint4 o;
        o.x = h2u(__floats2half2_rn(a.x, a.y));
        o.y = h2u(__floats2half2_rn(a.z, a.w));
        o.z = h2u(__floats2half2_rn(b.x, b.y));
        o.w = h2u(__floats2half2_rn(b.z, b.w));
        ((uint4*)DM)[i] = o;
    }
}

// ===========================================================================
// Fused projection GEMM (fp16 in, fp32 accum): C_z = A_z * W_z^T + bias_z
// Tile 128m x 64n x 64k, 3-stage cp.async, 8 warps (4m x 2n), ldmatrix frags.
// ===========================================================================
#define GBM 128
#define GBN 64
#define GBK 64
#define GKT (D_ / GBK)              // 8
#define GA(s) ((s) * 16384)         // A: 128 rows x 128B
#define GB(s) (49152 + (s) * 8192)  // W: 64 rows x 128B
#define GSM 73728

__global__ __launch_bounds__(256) void gemm3_kernel(
    const __half* __restrict__ A0, const __half* __restrict__ A1, const __half* __restrict__ A2,
    const __half* __restrict__ W0, const __half* __restrict__ W1, const __half* __restrict__ W2,
    const float* __restrict__ bp0, const float* __restrict__ bp1, const float* __restrict__ bp2,
    __half* __restrict__ Ch0, __half* __restrict__ Ch1, __half* __restrict__ Ch2,
    float* __restrict__ Cf, int heads)
{
    extern __shared__ char sm[];
    const uint32_t sb = smem_to_u32(sm);
    const int z = blockIdx.z;
    const __half* A    = (z == 0) ? A0 : (z == 1) ? A1 : A2;
    const __half* W    = (z == 0) ? W0 : (z == 1) ? W1 : W2;
    const float* bias  = (z == 0) ? bp0 : (z == 1) ? bp1 : bp2;
    __half* Ch         = (z == 0) ? Ch0 : (z == 1) ? Ch1 : Ch2;

    const int tid = threadIdx.x;
    const int lane = tid & 31, warp = tid >> 5;
    const int wm = warp >> 1, wn = warp & 1;
    const int g = lane >> 2, t = lane & 3;
    const int m0 = blockIdx.y * GBM, n0 = blockIdx.x * GBN;

    auto stage = [&](int kt, int s) {
        const __half* Ab = A + (size_t)m0 * D_ + kt * GBK;
#pragma unroll
        for (int i = 0; i < 4; ++i) {
            int ci = tid + 256 * i;
            int row = ci >> 3, ch = ci & 7;
            cp16(sb + GA(s) + row * 128 + ((ch ^ (row & 7)) << 4),
                 Ab + (size_t)row * D_ + ch * 8);
        }
        const __half* Wb = W + (size_t)n0 * D_ + kt * GBK;
#pragma unroll
        for (int i = 0; i < 2; ++i) {
            int ci = tid + 256 * i;
            int row = ci >> 3, ch = ci & 7;
            cp16(sb + GB(s) + row * 128 + ((ch ^ (row & 7)) << 4),
                 Wb + (size_t)row * D_ + ch * 8);
        }
        CP_COMMIT;
    };

    stage(0, 0);
    stage(1, 1);

    const int l7 = lane & 7;
    const int rowA = wm * 32 + l7 + ((lane >> 3) & 1) * 8;
    const int kchA = lane >> 4;
    const int rowB = wn * 32 + l7 + (lane >> 4) * 8;
    const int kchB = (lane >> 3) & 1;

    float acc[2][4][4] = {};

#pragma unroll 1
    for (int kt = 0; kt < GKT; ++kt) {
        if (kt < GKT - 1) { CP_WAIT(1); } else { CP_WAIT(0); }
        __syncthreads();
        if (kt + 2 < GKT) stage(kt + 2, (kt + 2) % 3);

        const uint32_t Ao = sb + GA(kt % 3), Bo = sb + GB(kt % 3);
#pragma unroll
        for (int kk = 0; kk < 4; ++kk) {
            uint32_t a[2][4], b[2][4];
#pragma unroll
            for (int mt = 0; mt < 2; ++mt)
                ldsm4(a[mt], Ao + (uint32_t)(rowA + mt * 16) * 128
                             + (((2 * kk + kchA) ^ l7) << 4));
#pragma unroll
            for (int ntp = 0; ntp < 2; ++ntp)
                ldsm4(b[ntp], Bo + (uint32_t)(rowB + ntp * 16) * 128
                              + (((2 * kk + kchB) ^ l7) << 4));
#pragma unroll
            for (int mt = 0; mt < 2; ++mt)
#pragma unroll
                for (int nt = 0; nt < 4; ++nt)
                    mma_f16(acc[mt][nt], a[mt], &b[nt >> 1][(nt & 1) * 2]);
        }
    }

    // Epilogue
#pragma unroll
    for (int mt = 0; mt < 2; ++mt) {
#pragma unroll
        for (int nt = 0; nt < 4; ++nt) {
            int n = n0 + wn * 32 + nt * 8 + 2 * t;
            float2 bv = *(const float2*)&bias[n];
            float2 r0, r1;
            r0.x = acc[mt][nt][0] + bv.x; r0.y = acc[mt][nt][1] + bv.y;
            r1.x = acc[mt][nt][2] + bv.x; r1.y = acc[mt][nt][3] + bv.y;
            int m_a = m0 + wm * 32 + mt * 16 + g;
            int m_b = m_a + 8;
            if (heads) {
                int h = n >> 6, dk = n & 63;
                int ba = m_a >> 10, la = m_a & (L_ - 1);
                int bb = m_b >> 10, lb = m_b & (L_ - 1);
                *(__half2*)&Ch[((size_t)(ba * H_ + h) * L_ + la) * DK_ + dk] =
                    __floats2half2_rn(r0.x, r0.y);
                *(__half2*)&Ch[((size_t)(bb * H_ + h) * L_ + lb) * DK_ + dk] =
                    __floats2half2_rn(r1.x, r1.y);
            } else {
                *(float2*)&Cf[(size_t)m_a * D_ + n] = r0;
                *(float2*)&Cf[(size_t)m_b * D_ + n] = r1;
            }
        }
    }
}

// ===========================================================================
// Flash attention, FA2-style: warp = 16 q-rows x ALL 64 keys (8m x 1n).
// P in registers via ex2.approx.f16x2 (direct fp16 fragments); row sums via
// ones-MMA (no shfl); dmc bias fragments via ldmatrix. ONE barrier per tile,
// 3-deep K/V/dmc cp.async ring. 256 threads, 128 q-rows per CTA.
// ===========================================================================
#define AQ 0                          // 128 x 128B = 16KB
#define AK(s) (16384 + (s) * 8192)    // 3 bufs
#define AV(s) (40960 + (s) * 8192)    // 3 bufs
#define ADM(s) (65536 + (s) * 16384)  // 3 bufs (128q x 64k fp16)
#define ASMs 114688                   // 112KB -> 2 CTAs/SM

__global__ __launch_bounds__(256, 2) void attn_kernel(
    const __half* __restrict__ Q, const __half* __restrict__ K,
    const __half* __restrict__ V, const __half* __restrict__ dmc,
    const float* __restrict__ logwb, __half* __restrict__ X)
{
    extern __shared__ char sm[];
    const uint32_t sb = smem_to_u32(sm);

    const int tid = threadIdx.x;
    const int lane = tid & 31, warp = tid >> 5;
    const int g = lane >> 2, t = lane & 3;
    const int l7 = lane & 7;
    const int bh = blockIdx.y;
    const int b = bh >> 3, h = bh & 7;
    const int q0 = blockIdx.x * 128;
    const float LOG2E = 1.4426950408889634f;
    const float wb2 = __expf(logwb[h]) * LOG2E;
    const float c1 = 0.125f * LOG2E;
    const int qr = warp * 16;                  // 0..112

    const __half* Qb = Q + (size_t)(bh * L_ + q0) * DK_;
    const __half* Kb = K + (size_t)bh * L_ * DK_;
    const __half* Vb = V + (size_t)bh * L_ * DK_;
    const __half* Db = dmc + (size_t)b * L_ * L_ + (size_t)q0 * L_;

    auto stageKVD = [&](int tile, int buf) {
        const __half* Kt = Kb + (size_t)tile * 64 * DK_;
        const __half* Vt = Vb + (size_t)tile * 64 * DK_;
        const __half* Dt = Db + tile * 64;
#pragma unroll
        for (int i = 0; i < 2; ++i) {          // K,V: 64 rows x 8 chunks
            int ci = tid + 256 * i;
            int row = ci >> 3, ch = ci & 7;
            uint32_t off = row * 128 + ((ch ^ (row & 7)) << 4);
            cp16(sb + AK(buf) + off, Kt + row * DK_ + ch * 8);
            cp16(sb + AV(buf) + off, Vt + row * DK_ + ch * 8);
        }
#pragma unroll
        for (int i = 0; i < 4; ++i) {          // dmc: 128 rows x 8 chunks
            int ci = tid + 256 * i;
            int row = ci >> 3, ch = ci & 7;
            uint32_t off = row * 128 + ((ch ^ (row & 7)) << 4);
            cp16(sb + ADM(buf) + off, Dt + (size_t)row * L_ + ch * 8);
        }
        CP_COMMIT;
    };

    // Stage Q (128 rows), then tiles 0 and 1
    {
#pragma unroll
        for (int i = 0; i < 4; ++i) {
            int ci = tid + 256 * i;
            int row = ci >> 3, ch = ci & 7;
            cp16(sb + AQ + row * 128 + ((ch ^ (row & 7)) << 4),
                 Qb + row * DK_ + ch * 8);
        }
        CP_COMMIT;
    }
    stageKVD(0, 0);
    stageKVD(1, 1);

    CP_WAIT(2);
    __syncthreads();

    // fragment geometry (identical pattern for Q and dmc loads)
    const int rowF = l7 + ((lane >> 3) & 1) * 8;   // within 16-row group
    const int kchF = lane >> 4;

    // Q fragments (kept in regs whole loop)
    uint32_t qa[4][4];
#pragma unroll
    for (int kk = 0; kk < 4; ++kk)
        ldsm4(qa[kk], sb + AQ + (uint32_t)(qr + rowF) * 128
                      + (((2 * kk + kchF) ^ l7) << 4));

    float o[8][4] = {};
    float ls[4] = {};                          // row-sum accumulator (ones-MMA)
    float mrow0 = -1e30f, mrow1 = -1e30f;
    const uint32_t ONESB[2] = {0x3C003C00u, 0x3C003C00u};  // 1.0h x4

    // K / V ldmatrix geometry
    const int keyB = l7 + (lane >> 4) * 8;     // + ntp*16 (K frags, 64 keys)
    const int kchB = (lane >> 3) & 1;
    const int keyV = l7 + ((lane >> 3) & 1) * 8;  // + kk*16 (V frags)
    const int dchV = lane >> 4;                // + ntp*2 (V d-chunks 0..7)

#pragma unroll 1
    for (int it = 0; it < 16; ++it) {
        if (it < 15) { CP_WAIT(1); } else { CP_WAIT(0); }
        __syncthreads();                       // tile `it` staged; buf (it-1)%3 free
        if (it + 2 < 16) stageKVD(it + 2, (it + 2) % 3);

        const uint32_t Ko = sb + AK(it % 3), Vo = sb + AV(it % 3);
        const uint32_t Do = sb + ADM(it % 3);

        // S = Q K^T : 16q x 64k per warp
        float s[8][4] = {};
#pragma unroll
        for (int kk = 0; kk < 4; ++kk) {
            uint32_t kb[4][4];
#pragma unroll
            for (int ntp = 0; ntp < 4; ++ntp)
                ldsm4(kb[ntp], Ko + (uint32_t)(keyB + ntp * 16) * 128
                               + (((2 * kk + kchB) ^ l7) << 4));
#pragma unroll
            for (int nt = 0; nt < 8; ++nt)
                mma_f16(s[nt], qa[kk], &kb[nt >> 1][(nt & 1) * 2]);
        }

        // dmc bias fragments via ldmatrix (C-fragment layout)
        uint32_t dd[4][4];
#pragma unroll
        for (int hh = 0; hh < 4; ++hh)
            ldsm4(dd[hh], Do + (uint32_t)(qr + rowF) * 128
                          + (((2 * hh + kchF) ^ l7) << 4));

        // s2 = qk*c1 - d*wb2 (log2 domain)
#pragma unroll
        for (int nt = 0; nt < 8; ++nt) {
            float2 d0 = __half22float2(*(__half2*)&dd[nt >> 1][(nt & 1) * 2]);
            float2 d1 = __half22float2(*(__half2*)&dd[nt >> 1][(nt & 1) * 2 + 1]);
            s[nt][0] = fmaf(s[nt][0], c1, -d0.x * wb2);
            s[nt][1] = fmaf(s[nt][1], c1, -d0.y * wb2);
            s[nt][2] = fmaf(s[nt][2], c1, -d1.x * wb2);
            s[nt][3] = fmaf(s[nt][3], c1, -d1.y * wb2);
        }

        // row max — fully intra-warp (warp owns all 64 keys)
        float tm0 = -1e30f, tm1 = -1e30f;
#pragma unroll
        for (int nt = 0; nt < 8; ++nt) {
            tm0 = fmaxf(tm0, fmaxf(s[nt][0], s[nt][1]));
            tm1 = fmaxf(tm1, fmaxf(s[nt][2], s[nt][3]));
        }
        tm0 = fmaxf(tm0, __shfl_xor_sync(0xffffffff, tm0, 1));
        tm0 = fmaxf(tm0, __shfl_xor_sync(0xffffffff, tm0, 2));
        tm1 = fmaxf(tm1, __shfl_xor_sync(0xffffffff, tm1, 1));
        tm1 = fmaxf(tm1, __shfl_xor_sync(0xffffffff, tm1, 2));

        float mn0 = fmaxf(mrow0, tm0);
        float mn1 = fmaxf(mrow1, tm1);
        float sc0 = ex2(mrow0 - mn0);
        float sc1 = ex2(mrow1 - mn1);
        mrow0 = mn0; mrow1 = mn1;

        // P = ex2(s - m) computed DIRECTLY in fp16x2 -> A-operand fragments
        uint32_t pa[4][4];
#pragma unroll
        for (int nt = 0; nt < 8; ++nt) {
            uint32_t lo = h2u(__floats2half2_rn(s[nt][0] - mn0, s[nt][1] - mn0));
            uint32_t hi = h2u(__floats2half2_rn(s[nt][2] - mn1, s[nt][3] - mn1));
            pa[nt >> 1][(nt & 1) * 2 + 0] = ex2_h2(lo);
            pa[nt >> 1][(nt & 1) * 2 + 1] = ex2_h2(hi);
        }

        // rescale O and row-sum accumulators
#pragma unroll
        for (int nt = 0; nt < 8; ++nt) {
            o[nt][0] *= sc0; o[nt][1] *= sc0;
            o[nt][2] *= sc1; o[nt][3] *= sc1;
        }
        ls[0] *= sc0; ls[1] *= sc0; ls[2] *= sc1; ls[3] *= sc1;

        // row sums via ones-MMA: every lane gets row sum in ls[0] (g), ls[2] (g+8)
#pragma unroll
        for (int kk = 0; kk < 4; ++kk)
            mma_f16(ls, pa[kk], ONESB);

        // O += P V : 16q x 64d per warp
#pragma unroll
        for (int kk = 0; kk < 4; ++kk) {
            uint32_t vb[4][4];
#pragma unroll
            for (int ntp = 0; ntp < 4; ++ntp)
                ldsm4t(vb[ntp], Vo + (uint32_t)(kk * 16 + keyV) * 128
                                + (((ntp * 2 + dchV) ^ l7) << 4));
#pragma unroll
            for (int nt = 0; nt < 8; ++nt)
                mma_f16(o[nt], pa[kk], &vb[nt >> 1][(nt & 1) * 2]);
        }
        // no trailing barrier: next iteration's sync covers buffer reuse
    }

    // Normalize, write X (fp16) in (B, L, D)
    float inv0 = 1.f / ls[0];
    float inv1 = 1.f / ls[2];
    const size_t xr0 = (size_t)(b * L_ + q0 + qr + g) * D_ + h * DK_;
    const size_t xr1 = xr0 + 8 * D_;
#pragma unroll
    for (int nt = 0; nt < 8; ++nt) {
        int c = nt * 8 + 2 * t;
        *(__half2*)&X[xr0 + c] = __floats2half2_rn(o[nt][0] * inv0, o[nt][1] * inv0);
        *(__half2*)&X[xr1 + c] = __floats2half2_rn(o[nt][2] * inv1, o[nt][3] * inv1);
    }
}

// ---------------------------------------------------------------------------
extern "C" void kernel_launch(void* const* d_in, const int* in_sizes, int n_in,
                              void* d_out, int out_size)
{
    const float* query = (const float*)d_in[0];
    const float* key_  = (const float*)d_in[1];
    const float* value = (const float*)d_in[2];
    const float* dist  = (const float*)d_in[3];
    const unsigned char* mask = (const unsigned char*)d_in[4];
    const float* Wq = (const float*)d_in[5];
    const float* bq = (const float*)d_in[6];
    const float* Wk = (const float*)d_in[7];
    const float* bk = (const float*)d_in[8];
    const float* Wv = (const float*)d_in[9];
    const float* bv = (const float*)d_in[10];
    const float* Wo = (const float*)d_in[11];
    const float* bo = (const float*)d_in[12];
    const float* logwb = (const float*)d_in[13];

    __half *Ah, *Wh, *Qp, *Kp, *Vp, *Xp, *Dp;
    cudaGetSymbolAddress((void**)&Ah, g_Ah);
    cudaGetSymbolAddress((void**)&Wh, g_Wh);
    cudaGetSymbolAddress((void**)&Qp, g_Q);
    cudaGetSymbolAddress((void**)&Kp, g_K);
    cudaGetSymbolAddress((void**)&Vp, g_V);
    cudaGetSymbolAddress((void**)&Xp, g_X);
    cudaGetSymbolAddress((void**)&Dp, g_DM);
    __half* A0 = Ah;            __half* A1 = Ah + (size_t)M_ * D_;
    __half* A2 = Ah + 2 * (size_t)M_ * D_;
    __half* W0 = Wh;            __half* W1 = Wh + (size_t)D_ * D_;
    __half* W2 = Wh + 2 * (size_t)D_ * D_;
    __half* W3 = Wh + 3 * (size_t)D_ * D_;

    cudaFuncSetAttribute(gemm3_kernel,
                         cudaFuncAttributeMaxDynamicSharedMemorySize, GSM);
    cudaFuncSetAttribute(attn_kernel,
                         cudaFuncAttributeMaxDynamicSharedMemorySize, ASMs);

    // One fused prep pass (input/weight fp16 conversion + dist/mask fold)
    prep_kernel<<<PREP_BLOCKS, 256>>>(
        query, key_, value, Wq, Wk, Wv, Wo, dist, mask, Ah, Wh, Dp);

    // Fused Q/K/V projections
    gemm3_kernel<<<dim3(D_ / GBN, M_ / GBM, 3), 256, GSM>>>(
        A0, A1, A2, W0, W1, W2, bq, bk, bv, Qp, Kp, Vp, nullptr, 1);

    attn_kernel<<<dim3(L_ / 128, B_ * H_), 256, ASMs>>>(
        Qp, Kp, Vp, Dp, logwb, Xp);

    // Output projection (fp32 out)
    gemm3_kernel<<<dim3(D_ / GBN, M_ / GBM, 1), 256, GSM>>>(
        Xp, Xp, Xp, W3, W3, W3, bo, bo, bo,
        nullptr, nullptr, nullptr, (float*)d_out, 0);
}